// round 1
// baseline (speedup 1.0000x reference)
#include <cuda_runtime.h>
#include <cstddef>

#define Bc 2
#define Sc 4096
#define Cc 2048
#define Hc 16
#define Dc 128
#define NSPLIT 8

// ---------------- scratch (device globals; no allocation) ----------------
__device__ float g_Q[(size_t)Bc * Hc * Sc * Dc];     // 64 MB, (b,h,s,d)
__device__ float g_K[(size_t)Bc * Hc * Sc * Dc];     // 64 MB
__device__ float g_V[(size_t)Bc * Hc * Sc * Dc];     // 64 MB
__device__ float g_ATT[(size_t)Bc * Sc * Cc];        // 64 MB, (b,s,c)
__device__ float g_VKpart[NSPLIT][(size_t)Bc * Hc * 129 * Dc];
__device__ float g_VK[(size_t)Bc * Hc * 129 * Dc];   // (bh, n[0..128], d)

// ---------------- big GEMM: C[m,n] = sum_k A[m,k] * W[n,k] + bias[n] -----
// MODE 0: plain write to out (row-major M x C)           (final Wo proj)
// MODE 1: RoPE + ReLU epilogue, write (b,h,s,d) layout   (Q, K)
// MODE 2: plain epilogue, write (b,h,s,d) layout         (V)
// out_sel: 0 -> dout param, 1 -> g_Q, 2 -> g_K, 3 -> g_V
template <int MODE>
__global__ void __launch_bounds__(256, 2) gemm_kernel(
    const float* __restrict__ A,   // nullptr -> g_ATT
    const float* __restrict__ W,
    const float* __restrict__ bias,
    const float* __restrict__ cosT,
    const float* __restrict__ sinT,
    float* __restrict__ dout,
    int out_sel,
    int Kdim)
{
    __shared__ float As[2][16][128];
    __shared__ float Bs[2][16][128];

    const float* Ap = A ? A : g_ATT;
    float* out = (out_sel == 1) ? g_Q : (out_sel == 2) ? g_K
               : (out_sel == 3) ? g_V : dout;

    const int tid = threadIdx.x;
    const int tx = tid & 15;        // n-group
    const int ty = tid >> 4;        // m-group
    const int m0 = blockIdx.y * 128;
    const int n0 = blockIdx.x * 128;

    const int lrow = tid >> 2;          // 0..63
    const int lk4  = (tid & 3) * 4;     // k sub-offset

    const float* aP0 = Ap + (size_t)(m0 + lrow) * Kdim + lk4;
    const float* aP1 = aP0 + (size_t)64 * Kdim;
    const float* wP0 = W  + (size_t)(n0 + lrow) * Kdim + lk4;
    const float* wP1 = wP0 + (size_t)64 * Kdim;

    float acc[8][8];
#pragma unroll
    for (int i = 0; i < 8; i++)
#pragma unroll
        for (int j = 0; j < 8; j++) acc[i][j] = 0.f;

    const int nt = Kdim >> 4;   // 128 tiles

    // preload tile 0 into buffer 0
    {
        float4 a0 = *(const float4*)aP0;
        float4 a1 = *(const float4*)aP1;
        float4 b0 = *(const float4*)wP0;
        float4 b1 = *(const float4*)wP1;
        As[0][lk4 + 0][lrow] = a0.x; As[0][lk4 + 1][lrow] = a0.y;
        As[0][lk4 + 2][lrow] = a0.z; As[0][lk4 + 3][lrow] = a0.w;
        As[0][lk4 + 0][lrow + 64] = a1.x; As[0][lk4 + 1][lrow + 64] = a1.y;
        As[0][lk4 + 2][lrow + 64] = a1.z; As[0][lk4 + 3][lrow + 64] = a1.w;
        Bs[0][lk4 + 0][lrow] = b0.x; Bs[0][lk4 + 1][lrow] = b0.y;
        Bs[0][lk4 + 2][lrow] = b0.z; Bs[0][lk4 + 3][lrow] = b0.w;
        Bs[0][lk4 + 0][lrow + 64] = b1.x; Bs[0][lk4 + 1][lrow + 64] = b1.y;
        Bs[0][lk4 + 2][lrow + 64] = b1.z; Bs[0][lk4 + 3][lrow + 64] = b1.w;
    }
    __syncthreads();

    for (int kt = 0; kt < nt; kt++) {
        const int buf = kt & 1;
        float4 na0, na1, nb0, nb1;
        const bool more = (kt + 1 < nt);
        if (more) {
            const int off = (kt + 1) << 4;
            na0 = *(const float4*)(aP0 + off);
            na1 = *(const float4*)(aP1 + off);
            nb0 = *(const float4*)(wP0 + off);
            nb1 = *(const float4*)(wP1 + off);
        }
#pragma unroll
        for (int k = 0; k < 16; k++) {
            float4 a0 = *(const float4*)&As[buf][k][ty * 8];
            float4 a1 = *(const float4*)&As[buf][k][ty * 8 + 4];
            float4 b0 = *(const float4*)&Bs[buf][k][tx * 8];
            float4 b1 = *(const float4*)&Bs[buf][k][tx * 8 + 4];
            float av[8] = {a0.x, a0.y, a0.z, a0.w, a1.x, a1.y, a1.z, a1.w};
            float bv[8] = {b0.x, b0.y, b0.z, b0.w, b1.x, b1.y, b1.z, b1.w};
#pragma unroll
            for (int i = 0; i < 8; i++)
#pragma unroll
                for (int j = 0; j < 8; j++)
                    acc[i][j] = fmaf(av[i], bv[j], acc[i][j]);
        }
        if (more) {
            const int nb = buf ^ 1;
            As[nb][lk4 + 0][lrow] = na0.x; As[nb][lk4 + 1][lrow] = na0.y;
            As[nb][lk4 + 2][lrow] = na0.z; As[nb][lk4 + 3][lrow] = na0.w;
            As[nb][lk4 + 0][lrow + 64] = na1.x; As[nb][lk4 + 1][lrow + 64] = na1.y;
            As[nb][lk4 + 2][lrow + 64] = na1.z; As[nb][lk4 + 3][lrow + 64] = na1.w;
            Bs[nb][lk4 + 0][lrow] = nb0.x; Bs[nb][lk4 + 1][lrow] = nb0.y;
            Bs[nb][lk4 + 2][lrow] = nb0.z; Bs[nb][lk4 + 3][lrow] = nb0.w;
            Bs[nb][lk4 + 0][lrow + 64] = nb1.x; Bs[nb][lk4 + 1][lrow + 64] = nb1.y;
            Bs[nb][lk4 + 2][lrow + 64] = nb1.z; Bs[nb][lk4 + 3][lrow + 64] = nb1.w;
        }
        __syncthreads();
    }

    // -------- epilogue --------
    if (MODE == 0) {
#pragma unroll
        for (int i = 0; i < 8; i++) {
            const int m = m0 + ty * 8 + i;
            float v[8];
#pragma unroll
            for (int j = 0; j < 8; j++)
                v[j] = acc[i][j] + bias[n0 + tx * 8 + j];
            float* o = out + (size_t)m * Cc + n0 + tx * 8;
            *(float4*)(o)     = make_float4(v[0], v[1], v[2], v[3]);
            *(float4*)(o + 4) = make_float4(v[4], v[5], v[6], v[7]);
        }
    } else {
        const int h = n0 >> 7;   // 128 cols per head, so block col == head
#pragma unroll
        for (int i = 0; i < 8; i++) {
            const int m = m0 + ty * 8 + i;
            const int b = m >> 12;          // / Sc
            const int s = m & (Sc - 1);
            float v[8];
#pragma unroll
            for (int j = 0; j < 8; j++)
                v[j] = acc[i][j] + bias[n0 + tx * 8 + j];
            if (MODE == 1) {
#pragma unroll
                for (int p = 0; p < 4; p++) {
                    const int de = tx * 8 + 2 * p;   // d within head (even)
                    const float c  = cosT[(size_t)s * Dc + de];
                    const float sn = sinT[(size_t)s * Dc + de];
                    const float te = v[2 * p], to = v[2 * p + 1];
                    v[2 * p]     = fmaxf(te * c - to * sn, 0.f);
                    v[2 * p + 1] = fmaxf(to * c + te * sn, 0.f);
                }
            }
            float* o = out + (((size_t)b * Hc + h) * Sc + s) * Dc + tx * 8;
            *(float4*)(o)     = make_float4(v[0], v[1], v[2], v[3]);
            *(float4*)(o + 4) = make_float4(v[4], v[5], v[6], v[7]);
        }
    }
}

// ------------- VK: per (b,h): VK[n,d] = sum_s V[s,n]*K[s,d]; row 128 = sum_s K[s,d]
__global__ void __launch_bounds__(256) vk_kernel()
{
    const int bh = blockIdx.x;           // 0..31
    const int sp = blockIdx.y;           // 0..NSPLIT-1
    const float* Vb = g_V + (size_t)bh * Sc * Dc;
    const float* Kb = g_K + (size_t)bh * Sc * Dc;

    __shared__ float Vs[16][128];
    __shared__ float Ks[16][128];

    const int tid = threadIdx.x;
    const int tx = tid & 15;   // d-group
    const int ty = tid >> 4;   // n-group
    const int lr = tid >> 5;   // 0..7
    const int lc = (tid & 31) * 4;

    float acc[8][8];
#pragma unroll
    for (int i = 0; i < 8; i++)
#pragma unroll
        for (int j = 0; j < 8; j++) acc[i][j] = 0.f;
    float csum = 0.f;

    const int schunk = Sc / NSPLIT;      // 512
    for (int st = 0; st < schunk / 16; st++) {
        const int s0 = sp * schunk + st * 16;
        __syncthreads();
        *(float4*)&Vs[lr][lc]     = *(const float4*)&Vb[(size_t)(s0 + lr) * Dc + lc];
        *(float4*)&Vs[lr + 8][lc] = *(const float4*)&Vb[(size_t)(s0 + lr + 8) * Dc + lc];
        *(float4*)&Ks[lr][lc]     = *(const float4*)&Kb[(size_t)(s0 + lr) * Dc + lc];
        *(float4*)&Ks[lr + 8][lc] = *(const float4*)&Kb[(size_t)(s0 + lr + 8) * Dc + lc];
        __syncthreads();
#pragma unroll
        for (int k = 0; k < 16; k++) {
            float4 a0 = *(const float4*)&Vs[k][ty * 8];
            float4 a1 = *(const float4*)&Vs[k][ty * 8 + 4];
            float4 b0 = *(const float4*)&Ks[k][tx * 8];
            float4 b1 = *(const float4*)&Ks[k][tx * 8 + 4];
            float av[8] = {a0.x, a0.y, a0.z, a0.w, a1.x, a1.y, a1.z, a1.w};
            float bv[8] = {b0.x, b0.y, b0.z, b0.w, b1.x, b1.y, b1.z, b1.w};
#pragma unroll
            for (int i = 0; i < 8; i++)
#pragma unroll
                for (int j = 0; j < 8; j++)
                    acc[i][j] = fmaf(av[i], bv[j], acc[i][j]);
        }
        if (tid < 128) {
#pragma unroll
            for (int k = 0; k < 16; k++) csum += Ks[k][tid];
        }
    }

    float* P = &g_VKpart[sp][(size_t)bh * 129 * Dc];
#pragma unroll
    for (int i = 0; i < 8; i++) {
        const int n = ty * 8 + i;
        *(float4*)&P[(size_t)n * Dc + tx * 8]     = make_float4(acc[i][0], acc[i][1], acc[i][2], acc[i][3]);
        *(float4*)&P[(size_t)n * Dc + tx * 8 + 4] = make_float4(acc[i][4], acc[i][5], acc[i][6], acc[i][7]);
    }
    if (tid < 128) P[(size_t)128 * Dc + tid] = csum;
}

__global__ void vk_reduce()
{
    const int i = blockIdx.x * 256 + threadIdx.x;
    if (i < Bc * Hc * 129 * Dc) {
        float s = 0.f;
#pragma unroll
        for (int p = 0; p < NSPLIT; p++) s += g_VKpart[p][i];
        g_VK[i] = s;
    }
}

// ------------- HS + divide: attn[b,s,h,n] = (sum_k VK[n,k]*Q[s,k]) / (sum_k VK[128,k]*Q[s,k] + eps)
__global__ void __launch_bounds__(256) attn_kernel()
{
    extern __shared__ float sm[];
    float* VKs = sm;                 // [128 k][132]: VKs[k*132 + n], n in 0..128
    float* Qs  = sm + 128 * 132;     // [128 k][132]: Qs[k*132 + s_local]
    float* den = Qs + 128 * 132;     // [128]

    const int bh = blockIdx.x;
    const int b = bh >> 4, h = bh & 15;
    const int s0 = blockIdx.y * 128;
    const int tid = threadIdx.x;
    const int tx = tid & 15;   // s-group
    const int ty = tid >> 4;   // n-group

    const float* VKg = g_VK + (size_t)bh * 129 * Dc;
    const float* Qg  = g_Q + ((size_t)bh * Sc + s0) * Dc;

    for (int idx = tid; idx < 129 * 128; idx += 256)
        VKs[(idx & 127) * 132 + (idx >> 7)] = VKg[idx];
    for (int idx = tid; idx < 128 * 128; idx += 256)
        Qs[(idx & 127) * 132 + (idx >> 7)] = Qg[idx];
    __syncthreads();

    float acc[8][8];
#pragma unroll
    for (int i = 0; i < 8; i++)
#pragma unroll
        for (int j = 0; j < 8; j++) acc[i][j] = 0.f;

#pragma unroll 4
    for (int k = 0; k < 128; k++) {
        float4 n0_ = *(const float4*)&VKs[k * 132 + ty * 8];
        float4 n1_ = *(const float4*)&VKs[k * 132 + ty * 8 + 4];
        float4 q0_ = *(const float4*)&Qs[k * 132 + tx * 8];
        float4 q1_ = *(const float4*)&Qs[k * 132 + tx * 8 + 4];
        float nv[8] = {n0_.x, n0_.y, n0_.z, n0_.w, n1_.x, n1_.y, n1_.z, n1_.w};
        float qv[8] = {q0_.x, q0_.y, q0_.z, q0_.w, q1_.x, q1_.y, q1_.z, q1_.w};
#pragma unroll
        for (int i = 0; i < 8; i++)
#pragma unroll
            for (int j = 0; j < 8; j++)
                acc[i][j] = fmaf(nv[i], qv[j], acc[i][j]);
    }

    if (tid < 128) {
        float d = 0.f;
#pragma unroll 4
        for (int k = 0; k < 128; k++)
            d = fmaf(VKs[k * 132 + 128], Qs[k * 132 + tid], d);
        den[tid] = d;
    }
    __syncthreads();

#pragma unroll
    for (int j = 0; j < 8; j++) {
        const int s = s0 + tx * 8 + j;
        const float inv = 1.0f / (den[tx * 8 + j] + 1e-15f);
        float* o = g_ATT + ((size_t)b * Sc + s) * Cc + h * Dc + ty * 8;
        *(float4*)(o)     = make_float4(acc[0][j] * inv, acc[1][j] * inv,
                                        acc[2][j] * inv, acc[3][j] * inv);
        *(float4*)(o + 4) = make_float4(acc[4][j] * inv, acc[5][j] * inv,
                                        acc[6][j] * inv, acc[7][j] * inv);
    }
}

// ---------------- launch ----------------
extern "C" void kernel_launch(void* const* d_in, const int* in_sizes, int n_in,
                              void* d_out, int out_size)
{
    (void)in_sizes; (void)n_in; (void)out_size;
    const float* x    = (const float*)d_in[0];
    const float* cosT = (const float*)d_in[1];
    const float* sinT = (const float*)d_in[2];
    const float* Wq   = (const float*)d_in[3];
    const float* bq   = (const float*)d_in[4];
    const float* Wk   = (const float*)d_in[5];
    const float* bk   = (const float*)d_in[6];
    const float* Wv   = (const float*)d_in[7];
    const float* bv   = (const float*)d_in[8];
    const float* Wo   = (const float*)d_in[9];
    const float* bo   = (const float*)d_in[10];
    float* out = (float*)d_out;

    const dim3 gg(Cc / 128, (Bc * Sc) / 128);   // (16, 64)

    gemm_kernel<1><<<gg, 256>>>(x, Wq, bq, cosT, sinT, nullptr, 1, Cc);
    gemm_kernel<1><<<gg, 256>>>(x, Wk, bk, cosT, sinT, nullptr, 2, Cc);
    gemm_kernel<2><<<gg, 256>>>(x, Wv, bv, nullptr, nullptr, nullptr, 3, Cc);

    vk_kernel<<<dim3(Bc * Hc, NSPLIT), 256>>>();
    vk_reduce<<<(Bc * Hc * 129 * Dc + 255) / 256, 256>>>();

    const int smem = (128 * 132 * 2 + 128) * sizeof(float);   // 135,680 B
    cudaFuncSetAttribute(attn_kernel, cudaFuncAttributeMaxDynamicSharedMemorySize, smem);
    attn_kernel<<<dim3(Bc * Hc, Sc / 128), 256, smem>>>();

    gemm_kernel<0><<<gg, 256>>>(nullptr, Wo, bo, nullptr, nullptr, out, 0, Cc);
}

// round 3
// speedup vs baseline: 1.6462x; 1.6462x over previous
#include <cuda_runtime.h>
#include <cuda_bf16.h>
#include <cstdint>
#include <cstddef>

#define Bc 2
#define Sc 4096
#define Cc 2048
#define Hc 16
#define Dc 128
#define NSPLIT 8

// ---------------- scratch (device globals; no allocation) ----------------
__device__ float g_Q[(size_t)Bc * Hc * Sc * Dc];     // (b,h,s,d)
__device__ float g_K[(size_t)Bc * Hc * Sc * Dc];
__device__ float g_V[(size_t)Bc * Hc * Sc * Dc];
__device__ float g_ATT[(size_t)Bc * Sc * Cc];        // (b,s,c)
__device__ float g_VKpart[NSPLIT][(size_t)Bc * Hc * 129 * Dc];
__device__ float g_VK[(size_t)Bc * Hc * 129 * Dc];

// ======================= helpers =======================
__device__ __forceinline__ uint32_t smem_u32(const void* p) {
    return (uint32_t)__cvta_generic_to_shared(p);
}

// bf16 split: hi = bf16x2(x,y); lo = bf16x2(x-hi.x, y-hi.y)
__device__ __forceinline__ void split2(float x, float y, uint32_t& hi, uint32_t& lo) {
    __nv_bfloat162 h = __floats2bfloat162_rn(x, y);
    float hx = __bfloat162float(h.x);
    float hy = __bfloat162float(h.y);
    __nv_bfloat162 l = __floats2bfloat162_rn(x - hx, y - hy);
    hi = *reinterpret_cast<uint32_t*>(&h);
    lo = *reinterpret_cast<uint32_t*>(&l);
}

#define LDSM_X4(r, addr) \
    asm volatile("ldmatrix.sync.aligned.m8n8.x4.shared.b16 {%0,%1,%2,%3}, [%4];" \
        : "=r"((r)[0]), "=r"((r)[1]), "=r"((r)[2]), "=r"((r)[3]) : "r"(addr))
#define LDSM_X2(r, addr) \
    asm volatile("ldmatrix.sync.aligned.m8n8.x2.shared.b16 {%0,%1}, [%2];" \
        : "=r"((r)[0]), "=r"((r)[1]) : "r"(addr))
#define MMA_BF16(d, a, b) \
    asm volatile("mma.sync.aligned.m16n8k16.row.col.f32.bf16.bf16.f32 " \
        "{%0,%1,%2,%3}, {%4,%5,%6,%7}, {%8,%9}, {%0,%1,%2,%3};" \
        : "+f"((d)[0]), "+f"((d)[1]), "+f"((d)[2]), "+f"((d)[3]) \
        : "r"((a)[0]), "r"((a)[1]), "r"((a)[2]), "r"((a)[3]), "r"((b)[0]), "r"((b)[1]))

// ======================= split-bf16 HMMA GEMM =======================
// C[m,n] = sum_k A[m,k]*W[n,k] + bias[n]
// CTA tile 128x128, K-chunk 32, 8 warps (4M x 2N), warp tile 32x64.
// SMEM: Ahi/Alo/Bhi/Blo, each 128 rows x 80B (32 bf16 + pad) = 10240B -> 40960B total.
#define RS 80
#define OFF_ALO 10240
#define OFF_BHI 20480
#define OFF_BLO 30720

template <int MODE>   // 0: row-major out; 1: RoPE+ReLU -> (b,h,s,d); 2: plain -> (b,h,s,d)
__global__ void __launch_bounds__(256, 2) mma_gemm(
    const float* __restrict__ A,      // nullptr -> g_ATT
    const float* __restrict__ W,
    const float* __restrict__ bias,
    const float* __restrict__ cosT,
    const float* __restrict__ sinT,
    float* __restrict__ dout,
    int out_sel)
{
    __shared__ __align__(16) char tile[40960];

    const float* Ap = A ? A : g_ATT;
    float* out = (out_sel == 1) ? g_Q : (out_sel == 2) ? g_K
               : (out_sel == 3) ? g_V : dout;

    const int tid = threadIdx.x;
    const int lane = tid & 31;
    const int wid = tid >> 5;
    const int m0 = blockIdx.y * 128;
    const int n0 = blockIdx.x * 128;
    const int warp_m = (wid >> 1) * 32;
    const int warp_n = (wid & 1) * 64;

    // ---- load mapping: each thread owns 16 consecutive floats of one row ----
    const int lrow = tid >> 1;          // 0..127
    const int lhalf = tid & 1;          // 0/1 -> float offset 0/16
    const float* pA = Ap + (size_t)(m0 + lrow) * Cc + lhalf * 16;
    const float* pB = W  + (size_t)(n0 + lrow) * Cc + lhalf * 16;
    const uint32_t stoff = (uint32_t)lrow * RS + lhalf * 32;

    const uint32_t sb = smem_u32(tile);
    // ldmatrix base addresses
    const uint32_t a_base = sb + (uint32_t)(warp_m + (lane & 15)) * RS + (lane >> 4) * 16;
    const uint32_t b_base = sb + OFF_BHI + (uint32_t)(warp_n + (lane & 7)) * RS + ((lane >> 3) & 1) * 16;

    float acc[2][8][4];
#pragma unroll
    for (int mt = 0; mt < 2; mt++)
#pragma unroll
        for (int nt = 0; nt < 8; nt++)
#pragma unroll
            for (int r = 0; r < 4; r++) acc[mt][nt][r] = 0.f;

    // prefetch chunk 0
    float4 pf[8];
#pragma unroll
    for (int i = 0; i < 4; i++) pf[i] = *(const float4*)(pA + i * 4);
#pragma unroll
    for (int i = 0; i < 4; i++) pf[4 + i] = *(const float4*)(pB + i * 4);

    for (int kt = 0; kt < Cc / 32; kt++) {
        __syncthreads();   // previous chunk's compute done; smem reusable

        // ---- convert + store current chunk ----
        {
            uint32_t h[8], l[8];
#pragma unroll
            for (int i = 0; i < 4; i++) {
                split2(pf[i].x, pf[i].y, h[2 * i], l[2 * i]);
                split2(pf[i].z, pf[i].w, h[2 * i + 1], l[2 * i + 1]);
            }
            *(uint4*)(tile + stoff)            = make_uint4(h[0], h[1], h[2], h[3]);
            *(uint4*)(tile + stoff + 16)       = make_uint4(h[4], h[5], h[6], h[7]);
            *(uint4*)(tile + OFF_ALO + stoff)      = make_uint4(l[0], l[1], l[2], l[3]);
            *(uint4*)(tile + OFF_ALO + stoff + 16) = make_uint4(l[4], l[5], l[6], l[7]);
#pragma unroll
            for (int i = 0; i < 4; i++) {
                split2(pf[4 + i].x, pf[4 + i].y, h[2 * i], l[2 * i]);
                split2(pf[4 + i].z, pf[4 + i].w, h[2 * i + 1], l[2 * i + 1]);
            }
            *(uint4*)(tile + OFF_BHI + stoff)      = make_uint4(h[0], h[1], h[2], h[3]);
            *(uint4*)(tile + OFF_BHI + stoff + 16) = make_uint4(h[4], h[5], h[6], h[7]);
            *(uint4*)(tile + OFF_BLO + stoff)      = make_uint4(l[0], l[1], l[2], l[3]);
            *(uint4*)(tile + OFF_BLO + stoff + 16) = make_uint4(l[4], l[5], l[6], l[7]);
        }
        __syncthreads();   // smem full

        // ---- issue next chunk's loads (latency hidden by mma below) ----
        if (kt + 1 < Cc / 32) {
            const int off = (kt + 1) * 32;
#pragma unroll
            for (int i = 0; i < 4; i++) pf[i] = *(const float4*)(pA + off + i * 4);
#pragma unroll
            for (int i = 0; i < 4; i++) pf[4 + i] = *(const float4*)(pB + off + i * 4);
        }

        // ---- compute: 2 k16 steps, 3 split passes ----
#pragma unroll
        for (int kk = 0; kk < 2; kk++) {
            uint32_t ah[2][4], al[2][4];
            LDSM_X4(ah[0], a_base + kk * 32);
            LDSM_X4(ah[1], a_base + kk * 32 + 16 * RS);
            LDSM_X4(al[0], a_base + OFF_ALO + kk * 32);
            LDSM_X4(al[1], a_base + OFF_ALO + kk * 32 + 16 * RS);
#pragma unroll
            for (int nt = 0; nt < 8; nt++) {
                uint32_t bh[2], bl[2];
                LDSM_X2(bh, b_base + kk * 32 + nt * 8 * RS);
                LDSM_X2(bl, b_base + (OFF_BLO - OFF_BHI) + kk * 32 + nt * 8 * RS);
                MMA_BF16(acc[0][nt], ah[0], bh);
                MMA_BF16(acc[1][nt], ah[1], bh);
                MMA_BF16(acc[0][nt], ah[0], bl);
                MMA_BF16(acc[1][nt], ah[1], bl);
                MMA_BF16(acc[0][nt], al[0], bh);
                MMA_BF16(acc[1][nt], al[1], bh);
            }
        }
    }

    // ---- epilogue: fragments -> bias (+RoPE/ReLU) -> global ----
    const int mrow = lane >> 2;
    const int cpair = (lane & 3) * 2;
#pragma unroll
    for (int mt = 0; mt < 2; mt++) {
#pragma unroll
        for (int rr = 0; rr < 2; rr++) {
            const int m = m0 + warp_m + mt * 16 + mrow + rr * 8;
            const int b = m >> 12;
            const int s = m & (Sc - 1);
#pragma unroll
            for (int nt = 0; nt < 8; nt++) {
                const int nl = warp_n + nt * 8 + cpair;   // 0..127
                float v0 = acc[mt][nt][rr * 2 + 0] + bias[n0 + nl];
                float v1 = acc[mt][nt][rr * 2 + 1] + bias[n0 + nl + 1];
                if (MODE == 1) {
                    const float cs = cosT[(size_t)s * Dc + nl];
                    const float sn = sinT[(size_t)s * Dc + nl];
                    const float e = v0 * cs - v1 * sn;
                    const float o_ = v1 * cs + v0 * sn;
                    v0 = fmaxf(e, 0.f);
                    v1 = fmaxf(o_, 0.f);
                }
                float2 w2 = make_float2(v0, v1);
                if (MODE == 0)
                    *(float2*)(out + (size_t)m * Cc + n0 + nl) = w2;
                else
                    *(float2*)(out + (((size_t)b * Hc + (n0 >> 7)) * Sc + s) * Dc + nl) = w2;
            }
        }
    }
}

// ======================= VK / attn (unchanged) =======================
__global__ void __launch_bounds__(256) vk_kernel()
{
    const int bh = blockIdx.x;
    const int sp = blockIdx.y;
    const float* Vb = g_V + (size_t)bh * Sc * Dc;
    const float* Kb = g_K + (size_t)bh * Sc * Dc;

    __shared__ float Vs[16][128];
    __shared__ float Ks[16][128];

    const int tid = threadIdx.x;
    const int tx = tid & 15;
    const int ty = tid >> 4;
    const int lr = tid >> 5;
    const int lc = (tid & 31) * 4;

    float acc[8][8];
#pragma unroll
    for (int i = 0; i < 8; i++)
#pragma unroll
        for (int j = 0; j < 8; j++) acc[i][j] = 0.f;
    float csum = 0.f;

    const int schunk = Sc / NSPLIT;
    for (int st = 0; st < schunk / 16; st++) {
        const int s0 = sp * schunk + st * 16;
        __syncthreads();
        *(float4*)&Vs[lr][lc]     = *(const float4*)&Vb[(size_t)(s0 + lr) * Dc + lc];
        *(float4*)&Vs[lr + 8][lc] = *(const float4*)&Vb[(size_t)(s0 + lr + 8) * Dc + lc];
        *(float4*)&Ks[lr][lc]     = *(const float4*)&Kb[(size_t)(s0 + lr) * Dc + lc];
        *(float4*)&Ks[lr + 8][lc] = *(const float4*)&Kb[(size_t)(s0 + lr + 8) * Dc + lc];
        __syncthreads();
#pragma unroll
        for (int k = 0; k < 16; k++) {
            float4 a0 = *(const float4*)&Vs[k][ty * 8];
            float4 a1 = *(const float4*)&Vs[k][ty * 8 + 4];
            float4 b0 = *(const float4*)&Ks[k][tx * 8];
            float4 b1 = *(const float4*)&Ks[k][tx * 8 + 4];
            float av[8] = {a0.x, a0.y, a0.z, a0.w, a1.x, a1.y, a1.z, a1.w};
            float bv[8] = {b0.x, b0.y, b0.z, b0.w, b1.x, b1.y, b1.z, b1.w};
#pragma unroll
            for (int i = 0; i < 8; i++)
#pragma unroll
                for (int j = 0; j < 8; j++)
                    acc[i][j] = fmaf(av[i], bv[j], acc[i][j]);
        }
        if (tid < 128) {
#pragma unroll
            for (int k = 0; k < 16; k++) csum += Ks[k][tid];
        }
    }

    float* P = &g_VKpart[sp][(size_t)bh * 129 * Dc];
#pragma unroll
    for (int i = 0; i < 8; i++) {
        const int n = ty * 8 + i;
        *(float4*)&P[(size_t)n * Dc + tx * 8]     = make_float4(acc[i][0], acc[i][1], acc[i][2], acc[i][3]);
        *(float4*)&P[(size_t)n * Dc + tx * 8 + 4] = make_float4(acc[i][4], acc[i][5], acc[i][6], acc[i][7]);
    }
    if (tid < 128) P[(size_t)128 * Dc + tid] = csum;
}

__global__ void vk_reduce()
{
    const int i = blockIdx.x * 256 + threadIdx.x;
    if (i < Bc * Hc * 129 * Dc) {
        float s = 0.f;
#pragma unroll
        for (int p = 0; p < NSPLIT; p++) s += g_VKpart[p][i];
        g_VK[i] = s;
    }
}

__global__ void __launch_bounds__(256) attn_kernel()
{
    extern __shared__ float sm[];
    float* VKs = sm;
    float* Qs  = sm + 128 * 132;
    float* den = Qs + 128 * 132;

    const int bh = blockIdx.x;
    const int b = bh >> 4, h = bh & 15;
    const int s0 = blockIdx.y * 128;
    const int tid = threadIdx.x;
    const int tx = tid & 15;
    const int ty = tid >> 4;

    const float* VKg = g_VK + (size_t)bh * 129 * Dc;
    const float* Qg  = g_Q + ((size_t)bh * Sc + s0) * Dc;

    for (int idx = tid; idx < 129 * 128; idx += 256)
        VKs[(idx & 127) * 132 + (idx >> 7)] = VKg[idx];
    for (int idx = tid; idx < 128 * 128; idx += 256)
        Qs[(idx & 127) * 132 + (idx >> 7)] = Qg[idx];
    __syncthreads();

    float acc[8][8];
#pragma unroll
    for (int i = 0; i < 8; i++)
#pragma unroll
        for (int j = 0; j < 8; j++) acc[i][j] = 0.f;

#pragma unroll 4
    for (int k = 0; k < 128; k++) {
        float4 n0_ = *(const float4*)&VKs[k * 132 + ty * 8];
        float4 n1_ = *(const float4*)&VKs[k * 132 + ty * 8 + 4];
        float4 q0_ = *(const float4*)&Qs[k * 132 + tx * 8];
        float4 q1_ = *(const float4*)&Qs[k * 132 + tx * 8 + 4];
        float nv[8] = {n0_.x, n0_.y, n0_.z, n0_.w, n1_.x, n1_.y, n1_.z, n1_.w};
        float qv[8] = {q0_.x, q0_.y, q0_.z, q0_.w, q1_.x, q1_.y, q1_.z, q1_.w};
#pragma unroll
        for (int i = 0; i < 8; i++)
#pragma unroll
            for (int j = 0; j < 8; j++)
                acc[i][j] = fmaf(nv[i], qv[j], acc[i][j]);
    }

    if (tid < 128) {
        float d = 0.f;
#pragma unroll 4
        for (int k = 0; k < 128; k++)
            d = fmaf(VKs[k * 132 + 128], Qs[k * 132 + tid], d);
        den[tid] = d;
    }
    __syncthreads();

#pragma unroll
    for (int j = 0; j < 8; j++) {
        const int s = s0 + tx * 8 + j;
        const float inv = 1.0f / (den[tx * 8 + j] + 1e-15f);
        float* o = g_ATT + ((size_t)b * Sc + s) * Cc + h * Dc + ty * 8;
        *(float4*)(o)     = make_float4(acc[0][j] * inv, acc[1][j] * inv,
                                        acc[2][j] * inv, acc[3][j] * inv);
        *(float4*)(o + 4) = make_float4(acc[4][j] * inv, acc[5][j] * inv,
                                        acc[6][j] * inv, acc[7][j] * inv);
    }
}

// ======================= launch =======================
extern "C" void kernel_launch(void* const* d_in, const int* in_sizes, int n_in,
                              void* d_out, int out_size)
{
    (void)in_sizes; (void)n_in; (void)out_size;
    const float* x    = (const float*)d_in[0];
    const float* cosT = (const float*)d_in[1];
    const float* sinT = (const float*)d_in[2];
    const float* Wq   = (const float*)d_in[3];
    const float* bq   = (const float*)d_in[4];
    const float* Wk   = (const float*)d_in[5];
    const float* bk   = (const float*)d_in[6];
    const float* Wv   = (const float*)d_in[7];
    const float* bv   = (const float*)d_in[8];
    const float* Wo   = (const float*)d_in[9];
    const float* bo   = (const float*)d_in[10];
    float* out = (float*)d_out;

    const dim3 gg(Cc / 128, (Bc * Sc) / 128);   // (16, 64)

    mma_gemm<1><<<gg, 256>>>(x, Wq, bq, cosT, sinT, nullptr, 1);
    mma_gemm<1><<<gg, 256>>>(x, Wk, bk, cosT, sinT, nullptr, 2);
    mma_gemm<2><<<gg, 256>>>(x, Wv, bv, nullptr, nullptr, nullptr, 3);

    vk_kernel<<<dim3(Bc * Hc, NSPLIT), 256>>>();
    vk_reduce<<<(Bc * Hc * 129 * Dc + 255) / 256, 256>>>();

    const int smem = (128 * 132 * 2 + 128) * sizeof(float);
    cudaFuncSetAttribute(attn_kernel, cudaFuncAttributeMaxDynamicSharedMemorySize, smem);
    attn_kernel<<<dim3(Bc * Hc, Sc / 128), 256, smem>>>();

    mma_gemm<0><<<gg, 256>>>(nullptr, Wo, bo, nullptr, nullptr, out, 0);
}

// round 4
// speedup vs baseline: 1.7019x; 1.0338x over previous
#include <cuda_runtime.h>
#include <cuda_bf16.h>
#include <cstdint>
#include <cstddef>

#define Bc 2
#define Sc 4096
#define Cc 2048
#define Hc 16
#define Dc 128
#define NSPLIT 8

// ---------------- scratch (device globals; no allocation) ----------------
__device__ float g_Q[(size_t)Bc * Hc * Sc * Dc];     // (b,h,s,d) fp32
__device__ float g_K[(size_t)Bc * Hc * Sc * Dc];
__device__ float g_V[(size_t)Bc * Hc * Sc * Dc];
__device__ float g_VKpart[NSPLIT][(size_t)Bc * Hc * 129 * Dc];
__device__ float g_VK[(size_t)Bc * Hc * 129 * Dc];
// split bf16 operand buffers
__device__ __nv_bfloat16 g_Xhi[(size_t)Bc * Sc * Cc];
__device__ __nv_bfloat16 g_Xlo[(size_t)Bc * Sc * Cc];
__device__ __nv_bfloat16 g_Whi[(size_t)4 * Cc * Cc];   // q,k,v,o
__device__ __nv_bfloat16 g_Wlo[(size_t)4 * Cc * Cc];
__device__ __nv_bfloat16 g_AThi[(size_t)Bc * Sc * Cc];
__device__ __nv_bfloat16 g_ATlo[(size_t)Bc * Sc * Cc];

// ======================= helpers =======================
__device__ __forceinline__ uint32_t smem_u32(const void* p) {
    return (uint32_t)__cvta_generic_to_shared(p);
}
__device__ __forceinline__ void split2(float x, float y, uint32_t& hi, uint32_t& lo) {
    __nv_bfloat162 h = __floats2bfloat162_rn(x, y);
    float hx = __bfloat162float(h.x);
    float hy = __bfloat162float(h.y);
    __nv_bfloat162 l = __floats2bfloat162_rn(x - hx, y - hy);
    hi = *reinterpret_cast<uint32_t*>(&h);
    lo = *reinterpret_cast<uint32_t*>(&l);
}
__device__ __forceinline__ void cpa16(uint32_t dst, const void* src) {
    asm volatile("cp.async.cg.shared.global [%0], [%1], 16;"
                 :: "r"(dst), "l"(__cvta_generic_to_global(src)) : "memory");
}
#define CP_COMMIT() asm volatile("cp.async.commit_group;" ::: "memory")
#define CP_WAIT2()  asm volatile("cp.async.wait_group 2;" ::: "memory")

#define LDSM_X4(r, addr) \
    asm volatile("ldmatrix.sync.aligned.m8n8.x4.shared.b16 {%0,%1,%2,%3}, [%4];" \
        : "=r"((r)[0]), "=r"((r)[1]), "=r"((r)[2]), "=r"((r)[3]) : "r"(addr))
#define MMA_BF16(d, a0, a1, a2, a3, b0, b1) \
    asm volatile("mma.sync.aligned.m16n8k16.row.col.f32.bf16.bf16.f32 " \
        "{%0,%1,%2,%3}, {%4,%5,%6,%7}, {%8,%9}, {%0,%1,%2,%3};" \
        : "+f"((d)[0]), "+f"((d)[1]), "+f"((d)[2]), "+f"((d)[3]) \
        : "r"(a0), "r"(a1), "r"(a2), "r"(a3), "r"(b0), "r"(b1))

// ======================= fp32 -> split bf16 converter =======================
__global__ void convert_split(const float* __restrict__ src,
                              __nv_bfloat16* __restrict__ hi,
                              __nv_bfloat16* __restrict__ lo, int n8)
{
    int i = blockIdx.x * blockDim.x + threadIdx.x;
    const int stride = gridDim.x * blockDim.x;
    for (; i < n8; i += stride) {
        float4 f0 = *(const float4*)(src + (size_t)i * 8);
        float4 f1 = *(const float4*)(src + (size_t)i * 8 + 4);
        uint32_t h[4], l[4];
        split2(f0.x, f0.y, h[0], l[0]);
        split2(f0.z, f0.w, h[1], l[1]);
        split2(f1.x, f1.y, h[2], l[2]);
        split2(f1.z, f1.w, h[3], l[3]);
        *(uint4*)(hi + (size_t)i * 8) = make_uint4(h[0], h[1], h[2], h[3]);
        *(uint4*)(lo + (size_t)i * 8) = make_uint4(l[0], l[1], l[2], l[3]);
    }
}

// ======================= pipelined split-bf16 HMMA GEMM =======================
// C[m,n] = sum_k A[m,k]*W[n,k] + bias[n]
// CTA 256x128, K-chunk 32, 4 cp.async stages (48KB each), 8 warps (4M x 2N), warp 64x64.
// SMEM per stage: Ahi 16K | Alo 16K | Bhi 8K | Blo 8K. Packed rows: 2 logical
// 64B rows per 128B physical row, chunk(16B) index = (cc + 4*(r&1)) ^ ((r>>1)&7).
#define KCH 32
#define NCHUNK (Cc / KCH)          // 64
#define STAGE_BYTES 49152
#define OFF_ALO 16384
#define OFF_BHI 32768
#define OFF_BLO 40960

template <int MODE>   // 0: row-major out; 1: RoPE+ReLU -> (b,h,s,d); 2: plain -> (b,h,s,d)
__global__ void __launch_bounds__(256, 1) mma_gemm(
    const __nv_bfloat16* __restrict__ Ahi, const __nv_bfloat16* __restrict__ Alo,
    const __nv_bfloat16* __restrict__ Bhi, const __nv_bfloat16* __restrict__ Blo,
    const float* __restrict__ bias,
    const float* __restrict__ cosT, const float* __restrict__ sinT,
    float* __restrict__ dout, int out_sel)
{
    extern __shared__ __align__(16) char dyn[];
    float* out = (out_sel == 1) ? g_Q : (out_sel == 2) ? g_K
               : (out_sel == 3) ? g_V : dout;

    const int tid = threadIdx.x;
    const int lane = tid & 31;
    const int wid = tid >> 5;
    const int m0 = blockIdx.y * 256;
    const int n0 = blockIdx.x * 128;
    const int warp_m = (wid >> 1) * 64;
    const int warp_n = (wid & 1) * 64;

    const uint32_t sb = smem_u32(dyn);

    // ---- per-thread cp.async dst offsets (stage-relative) + src row ptrs ----
    uint32_t dA[4], dB[2];
    {
        const int r = tid;
        const uint32_t pr = (uint32_t)(r >> 1) * 128, xr = (r >> 1) & 7, r4 = (r & 1) * 4;
#pragma unroll
        for (int cc = 0; cc < 4; cc++)
            dA[cc] = pr + ((((uint32_t)cc + r4) ^ xr) << 4);
        const int rb = tid & 127;
        const int cc0 = (tid >> 7) * 2;
        const uint32_t prb = (uint32_t)(rb >> 1) * 128, xb = (rb >> 1) & 7, rb4 = (rb & 1) * 4;
#pragma unroll
        for (int i = 0; i < 2; i++)
            dB[i] = OFF_BHI + prb + ((((uint32_t)(cc0 + i) + rb4) ^ xb) << 4);
    }
    const __nv_bfloat16* aH = Ahi + (size_t)(m0 + tid) * Cc;
    const __nv_bfloat16* aL = Alo + (size_t)(m0 + tid) * Cc;
    const __nv_bfloat16* bH = Bhi + (size_t)(n0 + (tid & 127)) * Cc;
    const __nv_bfloat16* bL = Blo + (size_t)(n0 + (tid & 127)) * Cc;
    const int bcc0 = (tid >> 7) * 2;

    // ---- per-thread ldmatrix address components ----
    uint32_t abase[4], axr[4];
    int acb[4];
#pragma unroll
    for (int mt = 0; mt < 4; mt++) {
        const int row = warp_m + mt * 16 + (lane & 15);
        abase[mt] = (uint32_t)(row >> 1) * 128;
        acb[mt] = (lane >> 4) + (row & 1) * 4;
        axr[mt] = (row >> 1) & 7;
    }
    uint32_t bbase[4], bxr[4];
    int bcb[4];
#pragma unroll
    for (int p = 0; p < 4; p++) {
        const int row = warp_n + p * 16 + ((lane >> 4) & 1) * 8 + (lane & 7);
        bbase[p] = OFF_BHI + (uint32_t)(row >> 1) * 128;
        bcb[p] = ((lane >> 3) & 1) + (row & 1) * 4;
        bxr[p] = (row >> 1) & 7;
    }

    float acc[4][8][4];
#pragma unroll
    for (int mt = 0; mt < 4; mt++)
#pragma unroll
        for (int nt = 0; nt < 8; nt++)
#pragma unroll
            for (int r = 0; r < 4; r++) acc[mt][nt][r] = 0.f;

    // ---- stage loader ----
    auto load_stage = [&](int buf, int kt) {
        const uint32_t st = sb + (uint32_t)buf * STAGE_BYTES;
        const int koff = kt * KCH;
#pragma unroll
        for (int cc = 0; cc < 4; cc++) {
            cpa16(st + dA[cc], aH + koff + cc * 8);
            cpa16(st + OFF_ALO + dA[cc], aL + koff + cc * 8);
        }
#pragma unroll
        for (int i = 0; i < 2; i++) {
            cpa16(st + dB[i], bH + koff + (bcc0 + i) * 8);
            cpa16(st + (OFF_BLO - OFF_BHI) + dB[i], bL + koff + (bcc0 + i) * 8);
        }
    };

    // prologue: fill 3 stages
#pragma unroll
    for (int s = 0; s < 3; s++) { load_stage(s, s); CP_COMMIT(); }

    for (int kt = 0; kt < NCHUNK; kt++) {
        CP_WAIT2();
        __syncthreads();
        if (kt + 3 < NCHUNK) load_stage((kt + 3) & 3, kt + 3);
        CP_COMMIT();

        const uint32_t st = sb + (uint32_t)(kt & 3) * STAGE_BYTES;
#pragma unroll
        for (int kk = 0; kk < 2; kk++) {
            uint32_t ah[4][4], al[4][4];
#pragma unroll
            for (int mt = 0; mt < 4; mt++) {
                const uint32_t a = st + abase[mt] +
                    ((((uint32_t)(kk * 2 + acb[mt])) ^ axr[mt]) << 4);
                LDSM_X4(ah[mt], a);
                LDSM_X4(al[mt], a + OFF_ALO);
            }
#pragma unroll
            for (int p = 0; p < 4; p++) {
                uint32_t bh[4], bl[4];
                const uint32_t b = st + bbase[p] +
                    ((((uint32_t)(kk * 2 + bcb[p])) ^ bxr[p]) << 4);
                LDSM_X4(bh, b);
                LDSM_X4(bl, b + (OFF_BLO - OFF_BHI));
#pragma unroll
                for (int mt = 0; mt < 4; mt++) {
                    MMA_BF16(acc[mt][2 * p],     ah[mt][0], ah[mt][1], ah[mt][2], ah[mt][3], bh[0], bh[1]);
                    MMA_BF16(acc[mt][2 * p + 1], ah[mt][0], ah[mt][1], ah[mt][2], ah[mt][3], bh[2], bh[3]);
                    MMA_BF16(acc[mt][2 * p],     ah[mt][0], ah[mt][1], ah[mt][2], ah[mt][3], bl[0], bl[1]);
                    MMA_BF16(acc[mt][2 * p + 1], ah[mt][0], ah[mt][1], ah[mt][2], ah[mt][3], bl[2], bl[3]);
                    MMA_BF16(acc[mt][2 * p],     al[mt][0], al[mt][1], al[mt][2], al[mt][3], bh[0], bh[1]);
                    MMA_BF16(acc[mt][2 * p + 1], al[mt][0], al[mt][1], al[mt][2], al[mt][3], bh[2], bh[3]);
                }
            }
        }
    }

    // ---- epilogue ----
    const int mrow = lane >> 2;
    const int cpair = (lane & 3) * 2;
#pragma unroll
    for (int mt = 0; mt < 4; mt++) {
#pragma unroll
        for (int rr = 0; rr < 2; rr++) {
            const int m = m0 + warp_m + mt * 16 + mrow + rr * 8;
            const int b = m >> 12;
            const int s = m & (Sc - 1);
#pragma unroll
            for (int nt = 0; nt < 8; nt++) {
                const int nl = warp_n + nt * 8 + cpair;
                float v0 = acc[mt][nt][rr * 2 + 0] + bias[n0 + nl];
                float v1 = acc[mt][nt][rr * 2 + 1] + bias[n0 + nl + 1];
                if (MODE == 1) {
                    const float cs = cosT[(size_t)s * Dc + nl];
                    const float sn = sinT[(size_t)s * Dc + nl];
                    const float e = v0 * cs - v1 * sn;
                    const float o_ = v1 * cs + v0 * sn;
                    v0 = fmaxf(e, 0.f);
                    v1 = fmaxf(o_, 0.f);
                }
                float2 w2 = make_float2(v0, v1);
                if (MODE == 0)
                    *(float2*)(out + (size_t)m * Cc + n0 + nl) = w2;
                else
                    *(float2*)(out + (((size_t)b * Hc + (n0 >> 7)) * Sc + s) * Dc + nl) = w2;
            }
        }
    }
}

// ======================= VK =======================
__global__ void __launch_bounds__(256) vk_kernel()
{
    const int bh = blockIdx.x;
    const int sp = blockIdx.y;
    const float* Vb = g_V + (size_t)bh * Sc * Dc;
    const float* Kb = g_K + (size_t)bh * Sc * Dc;

    __shared__ float Vs[16][128];
    __shared__ float Ks[16][128];

    const int tid = threadIdx.x;
    const int tx = tid & 15;
    const int ty = tid >> 4;
    const int lr = tid >> 5;
    const int lc = (tid & 31) * 4;

    float acc[8][8];
#pragma unroll
    for (int i = 0; i < 8; i++)
#pragma unroll
        for (int j = 0; j < 8; j++) acc[i][j] = 0.f;
    float csum = 0.f;

    const int schunk = Sc / NSPLIT;
    for (int st = 0; st < schunk / 16; st++) {
        const int s0 = sp * schunk + st * 16;
        __syncthreads();
        *(float4*)&Vs[lr][lc]     = *(const float4*)&Vb[(size_t)(s0 + lr) * Dc + lc];
        *(float4*)&Vs[lr + 8][lc] = *(const float4*)&Vb[(size_t)(s0 + lr + 8) * Dc + lc];
        *(float4*)&Ks[lr][lc]     = *(const float4*)&Kb[(size_t)(s0 + lr) * Dc + lc];
        *(float4*)&Ks[lr + 8][lc] = *(const float4*)&Kb[(size_t)(s0 + lr + 8) * Dc + lc];
        __syncthreads();
#pragma unroll
        for (int k = 0; k < 16; k++) {
            float4 a0 = *(const float4*)&Vs[k][ty * 8];
            float4 a1 = *(const float4*)&Vs[k][ty * 8 + 4];
            float4 b0 = *(const float4*)&Ks[k][tx * 8];
            float4 b1 = *(const float4*)&Ks[k][tx * 8 + 4];
            float av[8] = {a0.x, a0.y, a0.z, a0.w, a1.x, a1.y, a1.z, a1.w};
            float bv[8] = {b0.x, b0.y, b0.z, b0.w, b1.x, b1.y, b1.z, b1.w};
#pragma unroll
            for (int i = 0; i < 8; i++)
#pragma unroll
                for (int j = 0; j < 8; j++)
                    acc[i][j] = fmaf(av[i], bv[j], acc[i][j]);
        }
        if (tid < 128) {
#pragma unroll
            for (int k = 0; k < 16; k++) csum += Ks[k][tid];
        }
    }

    float* P = &g_VKpart[sp][(size_t)bh * 129 * Dc];
#pragma unroll
    for (int i = 0; i < 8; i++) {
        const int n = ty * 8 + i;
        *(float4*)&P[(size_t)n * Dc + tx * 8]     = make_float4(acc[i][0], acc[i][1], acc[i][2], acc[i][3]);
        *(float4*)&P[(size_t)n * Dc + tx * 8 + 4] = make_float4(acc[i][4], acc[i][5], acc[i][6], acc[i][7]);
    }
    if (tid < 128) P[(size_t)128 * Dc + tid] = csum;
}

__global__ void vk_reduce()
{
    const int i = blockIdx.x * 256 + threadIdx.x;
    if (i < Bc * Hc * 129 * Dc) {
        float s = 0.f;
#pragma unroll
        for (int p = 0; p < NSPLIT; p++) s += g_VKpart[p][i];
        g_VK[i] = s;
    }
}

// ------------- HS + divide; writes split bf16 directly into ATT buffers -------------
__global__ void __launch_bounds__(256) attn_kernel()
{
    extern __shared__ float sm[];
    float* VKs = sm;
    float* Qs  = sm + 128 * 132;
    float* den = Qs + 128 * 132;

    const int bh = blockIdx.x;
    const int b = bh >> 4, h = bh & 15;
    const int s0 = blockIdx.y * 128;
    const int tid = threadIdx.x;
    const int tx = tid & 15;
    const int ty = tid >> 4;

    const float* VKg = g_VK + (size_t)bh * 129 * Dc;
    const float* Qg  = g_Q + ((size_t)bh * Sc + s0) * Dc;

    for (int idx = tid; idx < 129 * 128; idx += 256)
        VKs[(idx & 127) * 132 + (idx >> 7)] = VKg[idx];
    for (int idx = tid; idx < 128 * 128; idx += 256)
        Qs[(idx & 127) * 132 + (idx >> 7)] = Qg[idx];
    __syncthreads();

    float acc[8][8];
#pragma unroll
    for (int i = 0; i < 8; i++)
#pragma unroll
        for (int j = 0; j < 8; j++) acc[i][j] = 0.f;

#pragma unroll 4
    for (int k = 0; k < 128; k++) {
        float4 n0_ = *(const float4*)&VKs[k * 132 + ty * 8];
        float4 n1_ = *(const float4*)&VKs[k * 132 + ty * 8 + 4];
        float4 q0_ = *(const float4*)&Qs[k * 132 + tx * 8];
        float4 q1_ = *(const float4*)&Qs[k * 132 + tx * 8 + 4];
        float nv[8] = {n0_.x, n0_.y, n0_.z, n0_.w, n1_.x, n1_.y, n1_.z, n1_.w};
        float qv[8] = {q0_.x, q0_.y, q0_.z, q0_.w, q1_.x, q1_.y, q1_.z, q1_.w};
#pragma unroll
        for (int i = 0; i < 8; i++)
#pragma unroll
            for (int j = 0; j < 8; j++)
                acc[i][j] = fmaf(nv[i], qv[j], acc[i][j]);
    }

    if (tid < 128) {
        float d = 0.f;
#pragma unroll 4
        for (int k = 0; k < 128; k++)
            d = fmaf(VKs[k * 132 + 128], Qs[k * 132 + tid], d);
        den[tid] = d;
    }
    __syncthreads();

#pragma unroll
    for (int j = 0; j < 8; j++) {
        const int s = s0 + tx * 8 + j;
        const float inv = 1.0f / (den[tx * 8 + j] + 1e-15f);
        const size_t o = ((size_t)b * Sc + s) * Cc + h * Dc + ty * 8;
        uint32_t hh[4], ll[4];
#pragma unroll
        for (int q = 0; q < 4; q++)
            split2(acc[2 * q][j] * inv, acc[2 * q + 1][j] * inv, hh[q], ll[q]);
        *(uint4*)(g_AThi + o) = make_uint4(hh[0], hh[1], hh[2], hh[3]);
        *(uint4*)(g_ATlo + o) = make_uint4(ll[0], ll[1], ll[2], ll[3]);
    }
}

// ======================= launch =======================
extern "C" void kernel_launch(void* const* d_in, const int* in_sizes, int n_in,
                              void* d_out, int out_size)
{
    (void)in_sizes; (void)n_in; (void)out_size;
    const float* x    = (const float*)d_in[0];
    const float* cosT = (const float*)d_in[1];
    const float* sinT = (const float*)d_in[2];
    const float* Wq   = (const float*)d_in[3];
    const float* bq   = (const float*)d_in[4];
    const float* Wk   = (const float*)d_in[5];
    const float* bk   = (const float*)d_in[6];
    const float* Wv   = (const float*)d_in[7];
    const float* bv   = (const float*)d_in[8];
    const float* Wo   = (const float*)d_in[9];
    const float* bo   = (const float*)d_in[10];
    float* out = (float*)d_out;

    // device-global addresses (host side)
    __nv_bfloat16 *xhi, *xlo, *whi, *wlo, *athi, *atlo;
    cudaGetSymbolAddress((void**)&xhi, g_Xhi);
    cudaGetSymbolAddress((void**)&xlo, g_Xlo);
    cudaGetSymbolAddress((void**)&whi, g_Whi);
    cudaGetSymbolAddress((void**)&wlo, g_Wlo);
    cudaGetSymbolAddress((void**)&athi, g_AThi);
    cudaGetSymbolAddress((void**)&atlo, g_ATlo);

    const size_t WSZ = (size_t)Cc * Cc;      // 4.19M
    // ---- pre-split conversions ----
    convert_split<<<2048, 256>>>(x, xhi, xlo, (int)((size_t)Bc * Sc * Cc / 8));
    convert_split<<<1024, 256>>>(Wq, whi + 0 * WSZ, wlo + 0 * WSZ, (int)(WSZ / 8));
    convert_split<<<1024, 256>>>(Wk, whi + 1 * WSZ, wlo + 1 * WSZ, (int)(WSZ / 8));
    convert_split<<<1024, 256>>>(Wv, whi + 2 * WSZ, wlo + 2 * WSZ, (int)(WSZ / 8));
    convert_split<<<1024, 256>>>(Wo, whi + 3 * WSZ, wlo + 3 * WSZ, (int)(WSZ / 8));

    const int gsm = 4 * STAGE_BYTES;   // 196608
    cudaFuncSetAttribute(mma_gemm<0>, cudaFuncAttributeMaxDynamicSharedMemorySize, gsm);
    cudaFuncSetAttribute(mma_gemm<1>, cudaFuncAttributeMaxDynamicSharedMemorySize, gsm);
    cudaFuncSetAttribute(mma_gemm<2>, cudaFuncAttributeMaxDynamicSharedMemorySize, gsm);

    const dim3 gg(Cc / 128, (Bc * Sc) / 256);   // (16, 32)

    mma_gemm<1><<<gg, 256, gsm>>>(xhi, xlo, whi + 0 * WSZ, wlo + 0 * WSZ, bq, cosT, sinT, nullptr, 1);
    mma_gemm<1><<<gg, 256, gsm>>>(xhi, xlo, whi + 1 * WSZ, wlo + 1 * WSZ, bk, cosT, sinT, nullptr, 2);
    mma_gemm<2><<<gg, 256, gsm>>>(xhi, xlo, whi + 2 * WSZ, wlo + 2 * WSZ, bv, nullptr, nullptr, nullptr, 3);

    vk_kernel<<<dim3(Bc * Hc, NSPLIT), 256>>>();
    vk_reduce<<<(Bc * Hc * 129 * Dc + 255) / 256, 256>>>();

    const int smem = (128 * 132 * 2 + 128) * sizeof(float);
    cudaFuncSetAttribute(attn_kernel, cudaFuncAttributeMaxDynamicSharedMemorySize, smem);
    attn_kernel<<<dim3(Bc * Hc, Sc / 128), 256, smem>>>();

    mma_gemm<0><<<gg, 256, gsm>>>(athi, atlo, whi + 3 * WSZ, wlo + 3 * WSZ, bo, nullptr, nullptr, out, 0);
}

// round 5
// speedup vs baseline: 1.9613x; 1.1524x over previous
#include <cuda_runtime.h>
#include <cuda_bf16.h>
#include <cstdint>
#include <cstddef>

#define Bc 2
#define Sc 4096
#define Cc 2048
#define Hc 16
#define Dc 128
#define NSPLIT 8

// ---------------- scratch (device globals; no allocation) ----------------
__device__ float g_Q[(size_t)Bc * Hc * Sc * Dc];     // (b,h,s,d) fp32
__device__ float g_K[(size_t)Bc * Hc * Sc * Dc];
__device__ float g_V[(size_t)Bc * Hc * Sc * Dc];
__device__ float g_VKpart[NSPLIT][(size_t)Bc * Hc * 129 * Dc];
__device__ float g_VK[(size_t)Bc * Hc * 129 * Dc];
// split bf16 operand buffers
__device__ __nv_bfloat16 g_Xhi[(size_t)Bc * Sc * Cc];
__device__ __nv_bfloat16 g_Xlo[(size_t)Bc * Sc * Cc];
__device__ __nv_bfloat16 g_Whi[(size_t)4 * Cc * Cc];   // q,k,v,o
__device__ __nv_bfloat16 g_Wlo[(size_t)4 * Cc * Cc];
__device__ __nv_bfloat16 g_AThi[(size_t)Bc * Sc * Cc];
__device__ __nv_bfloat16 g_ATlo[(size_t)Bc * Sc * Cc];

// ======================= helpers =======================
__device__ __forceinline__ uint32_t smem_u32(const void* p) {
    return (uint32_t)__cvta_generic_to_shared(p);
}
__device__ __forceinline__ void split2(float x, float y, uint32_t& hi, uint32_t& lo) {
    __nv_bfloat162 h = __floats2bfloat162_rn(x, y);
    float hx = __bfloat162float(h.x);
    float hy = __bfloat162float(h.y);
    __nv_bfloat162 l = __floats2bfloat162_rn(x - hx, y - hy);
    hi = *reinterpret_cast<uint32_t*>(&h);
    lo = *reinterpret_cast<uint32_t*>(&l);
}
__device__ __forceinline__ void cpa16(uint32_t dst, const void* src) {
    asm volatile("cp.async.cg.shared.global [%0], [%1], 16;"
                 :: "r"(dst), "l"(__cvta_generic_to_global(src)) : "memory");
}
#define CP_COMMIT() asm volatile("cp.async.commit_group;" ::: "memory")
#define CP_WAIT2()  asm volatile("cp.async.wait_group 2;" ::: "memory")

#define LDSM_X4(r, addr) \
    asm volatile("ldmatrix.sync.aligned.m8n8.x4.shared.b16 {%0,%1,%2,%3}, [%4];" \
        : "=r"((r)[0]), "=r"((r)[1]), "=r"((r)[2]), "=r"((r)[3]) : "r"(addr))
#define MMA_BF16(d, a0, a1, a2, a3, b0, b1) \
    asm volatile("mma.sync.aligned.m16n8k16.row.col.f32.bf16.bf16.f32 " \
        "{%0,%1,%2,%3}, {%4,%5,%6,%7}, {%8,%9}, {%0,%1,%2,%3};" \
        : "+f"((d)[0]), "+f"((d)[1]), "+f"((d)[2]), "+f"((d)[3]) \
        : "r"(a0), "r"(a1), "r"(a2), "r"(a3), "r"(b0), "r"(b1))

// ======================= fp32 -> split bf16 converter =======================
__global__ void convert_split(const float* __restrict__ src,
                              __nv_bfloat16* __restrict__ hi,
                              __nv_bfloat16* __restrict__ lo, int n8)
{
    int i = blockIdx.x * blockDim.x + threadIdx.x;
    const int stride = gridDim.x * blockDim.x;
    for (; i < n8; i += stride) {
        float4 f0 = *(const float4*)(src + (size_t)i * 8);
        float4 f1 = *(const float4*)(src + (size_t)i * 8 + 4);
        uint32_t h[4], l[4];
        split2(f0.x, f0.y, h[0], l[0]);
        split2(f0.z, f0.w, h[1], l[1]);
        split2(f1.x, f1.y, h[2], l[2]);
        split2(f1.z, f1.w, h[3], l[3]);
        *(uint4*)(hi + (size_t)i * 8) = make_uint4(h[0], h[1], h[2], h[3]);
        *(uint4*)(lo + (size_t)i * 8) = make_uint4(l[0], l[1], l[2], l[3]);
    }
}

// ======================= pipelined split-bf16 HMMA GEMM =======================
// CTA 256x128, K-chunk 32, 4 cp.async stages (48KB), 16 warps (8M x 2N), warp 32x64.
#define KCH 32
#define NCHUNK (Cc / KCH)          // 64
#define STAGE_BYTES 49152
#define OFF_ALO 16384
#define OFF_BHI 32768
#define OFF_BLO 40960
#define NT 512

template <int MODE>   // 0: row-major out; 1: RoPE+ReLU -> (b,h,s,d); 2: plain -> (b,h,s,d)
__global__ void __launch_bounds__(NT, 1) mma_gemm(
    const __nv_bfloat16* __restrict__ Ahi, const __nv_bfloat16* __restrict__ Alo,
    const __nv_bfloat16* __restrict__ Bhi, const __nv_bfloat16* __restrict__ Blo,
    const float* __restrict__ bias,
    const float* __restrict__ cosT, const float* __restrict__ sinT,
    float* __restrict__ dout, int out_sel)
{
    extern __shared__ __align__(16) char dyn[];
    float* out = (out_sel == 1) ? g_Q : (out_sel == 2) ? g_K
               : (out_sel == 3) ? g_V : dout;

    const int tid = threadIdx.x;
    const int lane = tid & 31;
    const int wid = tid >> 5;                 // 0..15
    const int m0 = blockIdx.y * 256;
    const int n0 = blockIdx.x * 128;
    const int warp_m = (wid >> 1) * 32;       // 8 m-groups
    const int warp_n = (wid & 1) * 64;        // 2 n-groups

    const uint32_t sb = smem_u32(dyn);

    // ---- cp.async dst offsets: A 2 chunks/thread, B 1 chunk/thread ----
    uint32_t dA[2], dB;
    {
        const int r = tid >> 1;                           // logical A row 0..255
        const uint32_t pr = (uint32_t)(r >> 1) * 128, xr = (r >> 1) & 7, r4 = (r & 1) * 4;
        const int cc0 = (tid & 1) * 2;
#pragma unroll
        for (int i = 0; i < 2; i++)
            dA[i] = pr + ((((uint32_t)(cc0 + i) + r4) ^ xr) << 4);
        const int rb = tid & 127;                          // logical B row
        const int ccb = tid >> 7;                          // chunk 0..3
        const uint32_t prb = (uint32_t)(rb >> 1) * 128, xb = (rb >> 1) & 7, rb4 = (rb & 1) * 4;
        dB = OFF_BHI + prb + ((((uint32_t)ccb + rb4) ^ xb) << 4);
    }
    const __nv_bfloat16* aH = Ahi + (size_t)(m0 + (tid >> 1)) * Cc;
    const __nv_bfloat16* aL = Alo + (size_t)(m0 + (tid >> 1)) * Cc;
    const __nv_bfloat16* bH = Bhi + (size_t)(n0 + (tid & 127)) * Cc;
    const __nv_bfloat16* bL = Blo + (size_t)(n0 + (tid & 127)) * Cc;
    const int acc0 = (tid & 1) * 2;
    const int bccb = tid >> 7;

    // ---- ldmatrix address components ----
    uint32_t abase[2], axr[2];
    int acb[2];
#pragma unroll
    for (int mt = 0; mt < 2; mt++) {
        const int row = warp_m + mt * 16 + (lane & 15);
        abase[mt] = (uint32_t)(row >> 1) * 128;
        acb[mt] = (lane >> 4) + (row & 1) * 4;
        axr[mt] = (row >> 1) & 7;
    }
    uint32_t bbase[4], bxr[4];
    int bcb[4];
#pragma unroll
    for (int p = 0; p < 4; p++) {
        const int row = warp_n + p * 16 + ((lane >> 4) & 1) * 8 + (lane & 7);
        bbase[p] = OFF_BHI + (uint32_t)(row >> 1) * 128;
        bcb[p] = ((lane >> 3) & 1) + (row & 1) * 4;
        bxr[p] = (row >> 1) & 7;
    }

    float acc[2][8][4];
#pragma unroll
    for (int mt = 0; mt < 2; mt++)
#pragma unroll
        for (int nt = 0; nt < 8; nt++)
#pragma unroll
            for (int r = 0; r < 4; r++) acc[mt][nt][r] = 0.f;

    auto load_stage = [&](int buf, int kt) {
        const uint32_t st = sb + (uint32_t)buf * STAGE_BYTES;
        const int koff = kt * KCH;
#pragma unroll
        for (int i = 0; i < 2; i++) {
            cpa16(st + dA[i], aH + koff + (acc0 + i) * 8);
            cpa16(st + OFF_ALO + dA[i], aL + koff + (acc0 + i) * 8);
        }
        cpa16(st + dB, bH + koff + bccb * 8);
        cpa16(st + (OFF_BLO - OFF_BHI) + dB, bL + koff + bccb * 8);
    };

#pragma unroll
    for (int s = 0; s < 3; s++) { load_stage(s, s); CP_COMMIT(); }

    for (int kt = 0; kt < NCHUNK; kt++) {
        CP_WAIT2();
        __syncthreads();
        if (kt + 3 < NCHUNK) load_stage((kt + 3) & 3, kt + 3);
        CP_COMMIT();

        const uint32_t st = sb + (uint32_t)(kt & 3) * STAGE_BYTES;
#pragma unroll
        for (int kk = 0; kk < 2; kk++) {
            uint32_t ah[2][4], al[2][4];
#pragma unroll
            for (int mt = 0; mt < 2; mt++) {
                const uint32_t a = st + abase[mt] +
                    ((((uint32_t)(kk * 2 + acb[mt])) ^ axr[mt]) << 4);
                LDSM_X4(ah[mt], a);
                LDSM_X4(al[mt], a + OFF_ALO);
            }
#pragma unroll
            for (int p = 0; p < 4; p++) {
                uint32_t bh[4], bl[4];
                const uint32_t b = st + bbase[p] +
                    ((((uint32_t)(kk * 2 + bcb[p])) ^ bxr[p]) << 4);
                LDSM_X4(bh, b);
                LDSM_X4(bl, b + (OFF_BLO - OFF_BHI));
#pragma unroll
                for (int mt = 0; mt < 2; mt++) {
                    MMA_BF16(acc[mt][2 * p],     ah[mt][0], ah[mt][1], ah[mt][2], ah[mt][3], bh[0], bh[1]);
                    MMA_BF16(acc[mt][2 * p + 1], ah[mt][0], ah[mt][1], ah[mt][2], ah[mt][3], bh[2], bh[3]);
                    MMA_BF16(acc[mt][2 * p],     ah[mt][0], ah[mt][1], ah[mt][2], ah[mt][3], bl[0], bl[1]);
                    MMA_BF16(acc[mt][2 * p + 1], ah[mt][0], ah[mt][1], ah[mt][2], ah[mt][3], bl[2], bl[3]);
                    MMA_BF16(acc[mt][2 * p],     al[mt][0], al[mt][1], al[mt][2], al[mt][3], bh[0], bh[1]);
                    MMA_BF16(acc[mt][2 * p + 1], al[mt][0], al[mt][1], al[mt][2], al[mt][3], bh[2], bh[3]);
                }
            }
        }
    }

    // ---- epilogue ----
    const int mrow = lane >> 2;
    const int cpair = (lane & 3) * 2;
#pragma unroll
    for (int mt = 0; mt < 2; mt++) {
#pragma unroll
        for (int rr = 0; rr < 2; rr++) {
            const int m = m0 + warp_m + mt * 16 + mrow + rr * 8;
            const int b = m >> 12;
            const int s = m & (Sc - 1);
#pragma unroll
            for (int nt = 0; nt < 8; nt++) {
                const int nl = warp_n + nt * 8 + cpair;
                float v0 = acc[mt][nt][rr * 2 + 0] + bias[n0 + nl];
                float v1 = acc[mt][nt][rr * 2 + 1] + bias[n0 + nl + 1];
                if (MODE == 1) {
                    const float cs = cosT[(size_t)s * Dc + nl];
                    const float sn = sinT[(size_t)s * Dc + nl];
                    const float e = v0 * cs - v1 * sn;
                    const float o_ = v1 * cs + v0 * sn;
                    v0 = fmaxf(e, 0.f);
                    v1 = fmaxf(o_, 0.f);
                }
                float2 w2 = make_float2(v0, v1);
                if (MODE == 0)
                    *(float2*)(out + (size_t)m * Cc + n0 + nl) = w2;
                else
                    *(float2*)(out + (((size_t)b * Hc + (n0 >> 7)) * Sc + s) * Dc + nl) = w2;
            }
        }
    }
}

// ======================= VK =======================
__global__ void __launch_bounds__(256) vk_kernel()
{
    const int bh = blockIdx.x;
    const int sp = blockIdx.y;
    const float* Vb = g_V + (size_t)bh * Sc * Dc;
    const float* Kb = g_K + (size_t)bh * Sc * Dc;

    __shared__ float Vs[16][128];
    __shared__ float Ks[16][128];

    const int tid = threadIdx.x;
    const int tx = tid & 15;
    const int ty = tid >> 4;
    const int lr = tid >> 5;
    const int lc = (tid & 31) * 4;

    float acc[8][8];
#pragma unroll
    for (int i = 0; i < 8; i++)
#pragma unroll
        for (int j = 0; j < 8; j++) acc[i][j] = 0.f;
    float csum = 0.f;

    const int schunk = Sc / NSPLIT;
    for (int st = 0; st < schunk / 16; st++) {
        const int s0 = sp * schunk + st * 16;
        __syncthreads();
        *(float4*)&Vs[lr][lc]     = *(const float4*)&Vb[(size_t)(s0 + lr) * Dc + lc];
        *(float4*)&Vs[lr + 8][lc] = *(const float4*)&Vb[(size_t)(s0 + lr + 8) * Dc + lc];
        *(float4*)&Ks[lr][lc]     = *(const float4*)&Kb[(size_t)(s0 + lr) * Dc + lc];
        *(float4*)&Ks[lr + 8][lc] = *(const float4*)&Kb[(size_t)(s0 + lr + 8) * Dc + lc];
        __syncthreads();
#pragma unroll
        for (int k = 0; k < 16; k++) {
            float4 a0 = *(const float4*)&Vs[k][ty * 8];
            float4 a1 = *(const float4*)&Vs[k][ty * 8 + 4];
            float4 b0 = *(const float4*)&Ks[k][tx * 8];
            float4 b1 = *(const float4*)&Ks[k][tx * 8 + 4];
            float av[8] = {a0.x, a0.y, a0.z, a0.w, a1.x, a1.y, a1.z, a1.w};
            float bv[8] = {b0.x, b0.y, b0.z, b0.w, b1.x, b1.y, b1.z, b1.w};
#pragma unroll
            for (int i = 0; i < 8; i++)
#pragma unroll
                for (int j = 0; j < 8; j++)
                    acc[i][j] = fmaf(av[i], bv[j], acc[i][j]);
        }
        if (tid < 128) {
#pragma unroll
            for (int k = 0; k < 16; k++) csum += Ks[k][tid];
        }
    }

    float* P = &g_VKpart[sp][(size_t)bh * 129 * Dc];
#pragma unroll
    for (int i = 0; i < 8; i++) {
        const int n = ty * 8 + i;
        *(float4*)&P[(size_t)n * Dc + tx * 8]     = make_float4(acc[i][0], acc[i][1], acc[i][2], acc[i][3]);
        *(float4*)&P[(size_t)n * Dc + tx * 8 + 4] = make_float4(acc[i][4], acc[i][5], acc[i][6], acc[i][7]);
    }
    if (tid < 128) P[(size_t)128 * Dc + tid] = csum;
}

__global__ void vk_reduce()
{
    const int i = blockIdx.x * 256 + threadIdx.x;
    if (i < Bc * Hc * 129 * Dc) {
        float s = 0.f;
#pragma unroll
        for (int p = 0; p < NSPLIT; p++) s += g_VKpart[p][i];
        g_VK[i] = s;
    }
}

// ------------- HS + divide; writes split bf16 into ATT buffers -------------
__global__ void __launch_bounds__(256) attn_kernel()
{
    extern __shared__ float sm[];
    float* VKs = sm;
    float* Qs  = sm + 128 * 132;
    float* den = Qs + 128 * 132;

    const int bh = blockIdx.x;
    const int b = bh >> 4, h = bh & 15;
    const int s0 = blockIdx.y * 128;
    const int tid = threadIdx.x;
    const int tx = tid & 15;
    const int ty = tid >> 4;

    const float* VKg = g_VK + (size_t)bh * 129 * Dc;
    const float* Qg  = g_Q + ((size_t)bh * Sc + s0) * Dc;

    for (int idx = tid; idx < 129 * 128; idx += 256)
        VKs[(idx & 127) * 132 + (idx >> 7)] = VKg[idx];
    for (int idx = tid; idx < 128 * 128; idx += 256)
        Qs[(idx & 127) * 132 + (idx >> 7)] = Qg[idx];
    __syncthreads();

    float acc[8][8];
#pragma unroll
    for (int i = 0; i < 8; i++)
#pragma unroll
        for (int j = 0; j < 8; j++) acc[i][j] = 0.f;

#pragma unroll 4
    for (int k = 0; k < 128; k++) {
        float4 n0_ = *(const float4*)&VKs[k * 132 + ty * 8];
        float4 n1_ = *(const float4*)&VKs[k * 132 + ty * 8 + 4];
        float4 q0_ = *(const float4*)&Qs[k * 132 + tx * 8];
        float4 q1_ = *(const float4*)&Qs[k * 132 + tx * 8 + 4];
        float nv[8] = {n0_.x, n0_.y, n0_.z, n0_.w, n1_.x, n1_.y, n1_.z, n1_.w};
        float qv[8] = {q0_.x, q0_.y, q0_.z, q0_.w, q1_.x, q1_.y, q1_.z, q1_.w};
#pragma unroll
        for (int i = 0; i < 8; i++)
#pragma unroll
            for (int j = 0; j < 8; j++)
                acc[i][j] = fmaf(nv[i], qv[j], acc[i][j]);
    }

    if (tid < 128) {
        float d = 0.f;
#pragma unroll 4
        for (int k = 0; k < 128; k++)
            d = fmaf(VKs[k * 132 + 128], Qs[k * 132 + tid], d);
        den[tid] = d;
    }
    __syncthreads();

#pragma unroll
    for (int j = 0; j < 8; j++) {
        const int s = s0 + tx * 8 + j;
        const float inv = 1.0f / (den[tx * 8 + j] + 1e-15f);
        const size_t o = ((size_t)b * Sc + s) * Cc + h * Dc + ty * 8;
        uint32_t hh[4], ll[4];
#pragma unroll
        for (int q = 0; q < 4; q++)
            split2(acc[2 * q][j] * inv, acc[2 * q + 1][j] * inv, hh[q], ll[q]);
        *(uint4*)(g_AThi + o) = make_uint4(hh[0], hh[1], hh[2], hh[3]);
        *(uint4*)(g_ATlo + o) = make_uint4(ll[0], ll[1], ll[2], ll[3]);
    }
}

// ======================= launch =======================
extern "C" void kernel_launch(void* const* d_in, const int* in_sizes, int n_in,
                              void* d_out, int out_size)
{
    (void)in_sizes; (void)n_in; (void)out_size;
    const float* x    = (const float*)d_in[0];
    const float* cosT = (const float*)d_in[1];
    const float* sinT = (const float*)d_in[2];
    const float* Wq   = (const float*)d_in[3];
    const float* bq   = (const float*)d_in[4];
    const float* Wk   = (const float*)d_in[5];
    const float* bk   = (const float*)d_in[6];
    const float* Wv   = (const float*)d_in[7];
    const float* bv   = (const float*)d_in[8];
    const float* Wo   = (const float*)d_in[9];
    const float* bo   = (const float*)d_in[10];
    float* out = (float*)d_out;

    __nv_bfloat16 *xhi, *xlo, *whi, *wlo, *athi, *atlo;
    cudaGetSymbolAddress((void**)&xhi, g_Xhi);
    cudaGetSymbolAddress((void**)&xlo, g_Xlo);
    cudaGetSymbolAddress((void**)&whi, g_Whi);
    cudaGetSymbolAddress((void**)&wlo, g_Wlo);
    cudaGetSymbolAddress((void**)&athi, g_AThi);
    cudaGetSymbolAddress((void**)&atlo, g_ATlo);

    const size_t WSZ = (size_t)Cc * Cc;
    convert_split<<<2048, 256>>>(x, xhi, xlo, (int)((size_t)Bc * Sc * Cc / 8));
    convert_split<<<1024, 256>>>(Wq, whi + 0 * WSZ, wlo + 0 * WSZ, (int)(WSZ / 8));
    convert_split<<<1024, 256>>>(Wk, whi + 1 * WSZ, wlo + 1 * WSZ, (int)(WSZ / 8));
    convert_split<<<1024, 256>>>(Wv, whi + 2 * WSZ, wlo + 2 * WSZ, (int)(WSZ / 8));
    convert_split<<<1024, 256>>>(Wo, whi + 3 * WSZ, wlo + 3 * WSZ, (int)(WSZ / 8));

    const int gsm = 4 * STAGE_BYTES;   // 196608
    cudaFuncSetAttribute(mma_gemm<0>, cudaFuncAttributeMaxDynamicSharedMemorySize, gsm);
    cudaFuncSetAttribute(mma_gemm<1>, cudaFuncAttributeMaxDynamicSharedMemorySize, gsm);
    cudaFuncSetAttribute(mma_gemm<2>, cudaFuncAttributeMaxDynamicSharedMemorySize, gsm);

    const dim3 gg(Cc / 128, (Bc * Sc) / 256);   // (16, 32)

    mma_gemm<1><<<gg, NT, gsm>>>(xhi, xlo, whi + 0 * WSZ, wlo + 0 * WSZ, bq, cosT, sinT, nullptr, 1);
    mma_gemm<1><<<gg, NT, gsm>>>(xhi, xlo, whi + 1 * WSZ, wlo + 1 * WSZ, bk, cosT, sinT, nullptr, 2);
    mma_gemm<2><<<gg, NT, gsm>>>(xhi, xlo, whi + 2 * WSZ, wlo + 2 * WSZ, bv, nullptr, nullptr, nullptr, 3);

    vk_kernel<<<dim3(Bc * Hc, NSPLIT), 256>>>();
    vk_reduce<<<(Bc * Hc * 129 * Dc + 255) / 256, 256>>>();

    const int smem = (128 * 132 * 2 + 128) * sizeof(float);
    cudaFuncSetAttribute(attn_kernel, cudaFuncAttributeMaxDynamicSharedMemorySize, smem);
    attn_kernel<<<dim3(Bc * Hc, Sc / 128), 256, smem>>>();

    mma_gemm<0><<<gg, NT, gsm>>>(athi, atlo, whi + 3 * WSZ, wlo + 3 * WSZ, bo, nullptr, nullptr, out, 0);
}

// round 6
// speedup vs baseline: 2.7547x; 1.4045x over previous
#include <cuda_runtime.h>
#include <cuda_fp16.h>
#include <cstdint>
#include <cstddef>

#define Bc 2
#define Sc 4096
#define Cc 2048
#define Hc 16
#define Dc 128
#define NSPLIT 8

// ---------------- scratch (device globals; no allocation) ----------------
__device__ float g_Q[(size_t)Bc * Hc * Sc * Dc];     // (b,h,s,d) fp32
__device__ float g_K[(size_t)Bc * Hc * Sc * Dc];
__device__ float g_V[(size_t)Bc * Hc * Sc * Dc];
__device__ float g_VKpart[NSPLIT][(size_t)Bc * Hc * 129 * Dc];
__device__ float g_VK[(size_t)Bc * Hc * 129 * Dc];
// fp16 operand buffers
__device__ __half g_Xhi[(size_t)Bc * Sc * Cc];
__device__ __half g_Whi[(size_t)4 * Cc * Cc];   // q,k,v,o
__device__ __half g_Wlo[(size_t)4 * Cc * Cc];
__device__ __half g_AThi[(size_t)Bc * Sc * Cc];

// ======================= helpers =======================
__device__ __forceinline__ uint32_t smem_u32(const void* p) {
    return (uint32_t)__cvta_generic_to_shared(p);
}
__device__ __forceinline__ uint32_t pack_h2(float x, float y) {
    __half2 h = __floats2half2_rn(x, y);
    return *reinterpret_cast<uint32_t*>(&h);
}
__device__ __forceinline__ void split2h(float x, float y, uint32_t& hi, uint32_t& lo) {
    __half2 h = __floats2half2_rn(x, y);
    float hx = __half2float(h.x);
    float hy = __half2float(h.y);
    __half2 l = __floats2half2_rn(x - hx, y - hy);
    hi = *reinterpret_cast<uint32_t*>(&h);
    lo = *reinterpret_cast<uint32_t*>(&l);
}
__device__ __forceinline__ void cpa16(uint32_t dst, const void* src) {
    asm volatile("cp.async.cg.shared.global [%0], [%1], 16;"
                 :: "r"(dst), "l"(__cvta_generic_to_global(src)) : "memory");
}
#define CP_COMMIT() asm volatile("cp.async.commit_group;" ::: "memory")
#define CP_WAIT2()  asm volatile("cp.async.wait_group 2;" ::: "memory")

#define LDSM_X4(r, addr) \
    asm volatile("ldmatrix.sync.aligned.m8n8.x4.shared.b16 {%0,%1,%2,%3}, [%4];" \
        : "=r"((r)[0]), "=r"((r)[1]), "=r"((r)[2]), "=r"((r)[3]) : "r"(addr))
#define MMA_F16(d, a0, a1, a2, a3, b0, b1) \
    asm volatile("mma.sync.aligned.m16n8k16.row.col.f32.f16.f16.f32 " \
        "{%0,%1,%2,%3}, {%4,%5,%6,%7}, {%8,%9}, {%0,%1,%2,%3};" \
        : "+f"((d)[0]), "+f"((d)[1]), "+f"((d)[2]), "+f"((d)[3]) \
        : "r"(a0), "r"(a1), "r"(a2), "r"(a3), "r"(b0), "r"(b1))

// ======================= fp32 -> fp16 converters =======================
__global__ void convert_hi(const float* __restrict__ src,
                           __half* __restrict__ hi, int n8)
{
    int i = blockIdx.x * blockDim.x + threadIdx.x;
    const int stride = gridDim.x * blockDim.x;
    for (; i < n8; i += stride) {
        float4 f0 = *(const float4*)(src + (size_t)i * 8);
        float4 f1 = *(const float4*)(src + (size_t)i * 8 + 4);
        *(uint4*)(hi + (size_t)i * 8) = make_uint4(
            pack_h2(f0.x, f0.y), pack_h2(f0.z, f0.w),
            pack_h2(f1.x, f1.y), pack_h2(f1.z, f1.w));
    }
}
__global__ void convert_hilo(const float* __restrict__ src,
                             __half* __restrict__ hi,
                             __half* __restrict__ lo, int n8)
{
    int i = blockIdx.x * blockDim.x + threadIdx.x;
    const int stride = gridDim.x * blockDim.x;
    for (; i < n8; i += stride) {
        float4 f0 = *(const float4*)(src + (size_t)i * 8);
        float4 f1 = *(const float4*)(src + (size_t)i * 8 + 4);
        uint32_t h[4], l[4];
        split2h(f0.x, f0.y, h[0], l[0]);
        split2h(f0.z, f0.w, h[1], l[1]);
        split2h(f1.x, f1.y, h[2], l[2]);
        split2h(f1.z, f1.w, h[3], l[3]);
        *(uint4*)(hi + (size_t)i * 8) = make_uint4(h[0], h[1], h[2], h[3]);
        *(uint4*)(lo + (size_t)i * 8) = make_uint4(l[0], l[1], l[2], l[3]);
    }
}

// ======================= pipelined 2-pass fp16 HMMA GEMM =======================
// C[m,n] = sum_k A[m,k] * (Whi[n,k] + Wlo[n,k]) + bias[n]
// CTA 256x128, K-chunk 32, 4 cp.async stages (32KB), 16 warps (8M x 2N), warp 32x64.
#define KCH 32
#define NCHUNK (Cc / KCH)          // 64
#define STAGE_BYTES 32768
#define OFF_BHI 16384
#define OFF_BLO 24576
#define NT 512

template <int MODE>   // 0: row-major out; 1: RoPE+ReLU -> (b,h,s,d); 2: plain -> (b,h,s,d)
__global__ void __launch_bounds__(NT, 1) mma_gemm(
    const __half* __restrict__ Ahi,
    const __half* __restrict__ Bhi, const __half* __restrict__ Blo,
    const float* __restrict__ bias,
    const float* __restrict__ cosT, const float* __restrict__ sinT,
    float* __restrict__ dout, int out_sel)
{
    extern __shared__ __align__(16) char dyn[];
    float* out = (out_sel == 1) ? g_Q : (out_sel == 2) ? g_K
               : (out_sel == 3) ? g_V : dout;

    const int tid = threadIdx.x;
    const int lane = tid & 31;
    const int wid = tid >> 5;                 // 0..15
    const int m0 = blockIdx.y * 256;
    const int n0 = blockIdx.x * 128;
    const int warp_m = (wid >> 1) * 32;       // 8 m-groups
    const int warp_n = (wid & 1) * 64;        // 2 n-groups

    const uint32_t sb = smem_u32(dyn);

    // ---- cp.async dst offsets: A 2 chunks/thread (hi only), B 1 chunk hi + 1 lo ----
    uint32_t dA[2], dB;
    {
        const int r = tid >> 1;                           // logical A row 0..255
        const uint32_t pr = (uint32_t)(r >> 1) * 128, xr = (r >> 1) & 7, r4 = (r & 1) * 4;
        const int cc0 = (tid & 1) * 2;
#pragma unroll
        for (int i = 0; i < 2; i++)
            dA[i] = pr + ((((uint32_t)(cc0 + i) + r4) ^ xr) << 4);
        const int rb = tid & 127;                          // logical B row
        const int ccb = tid >> 7;                          // chunk 0..3
        const uint32_t prb = (uint32_t)(rb >> 1) * 128, xb = (rb >> 1) & 7, rb4 = (rb & 1) * 4;
        dB = OFF_BHI + prb + ((((uint32_t)ccb + rb4) ^ xb) << 4);
    }
    const __half* aH = Ahi + (size_t)(m0 + (tid >> 1)) * Cc;
    const __half* bH = Bhi + (size_t)(n0 + (tid & 127)) * Cc;
    const __half* bL = Blo + (size_t)(n0 + (tid & 127)) * Cc;
    const int acc0 = (tid & 1) * 2;
    const int bccb = tid >> 7;

    // ---- ldmatrix address components ----
    uint32_t abase[2], axr[2];
    int acb[2];
#pragma unroll
    for (int mt = 0; mt < 2; mt++) {
        const int row = warp_m + mt * 16 + (lane & 15);
        abase[mt] = (uint32_t)(row >> 1) * 128;
        acb[mt] = (lane >> 4) + (row & 1) * 4;
        axr[mt] = (row >> 1) & 7;
    }
    uint32_t bbase[4], bxr[4];
    int bcb[4];
#pragma unroll
    for (int p = 0; p < 4; p++) {
        const int row = warp_n + p * 16 + ((lane >> 4) & 1) * 8 + (lane & 7);
        bbase[p] = OFF_BHI + (uint32_t)(row >> 1) * 128;
        bcb[p] = ((lane >> 3) & 1) + (row & 1) * 4;
        bxr[p] = (row >> 1) & 7;
    }

    float acc[2][8][4];
#pragma unroll
    for (int mt = 0; mt < 2; mt++)
#pragma unroll
        for (int nt = 0; nt < 8; nt++)
#pragma unroll
            for (int r = 0; r < 4; r++) acc[mt][nt][r] = 0.f;

    auto load_stage = [&](int buf, int kt) {
        const uint32_t st = sb + (uint32_t)buf * STAGE_BYTES;
        const int koff = kt * KCH;
#pragma unroll
        for (int i = 0; i < 2; i++)
            cpa16(st + dA[i], aH + koff + (acc0 + i) * 8);
        cpa16(st + dB, bH + koff + bccb * 8);
        cpa16(st + (OFF_BLO - OFF_BHI) + dB, bL + koff + bccb * 8);
    };

#pragma unroll
    for (int s = 0; s < 3; s++) { load_stage(s, s); CP_COMMIT(); }

    for (int kt = 0; kt < NCHUNK; kt++) {
        CP_WAIT2();
        __syncthreads();
        if (kt + 3 < NCHUNK) load_stage((kt + 3) & 3, kt + 3);
        CP_COMMIT();

        const uint32_t st = sb + (uint32_t)(kt & 3) * STAGE_BYTES;
#pragma unroll
        for (int kk = 0; kk < 2; kk++) {
            uint32_t ah[2][4];
#pragma unroll
            for (int mt = 0; mt < 2; mt++) {
                const uint32_t a = st + abase[mt] +
                    ((((uint32_t)(kk * 2 + acb[mt])) ^ axr[mt]) << 4);
                LDSM_X4(ah[mt], a);
            }
#pragma unroll
            for (int p = 0; p < 4; p++) {
                uint32_t bh[4], bl[4];
                const uint32_t b = st + bbase[p] +
                    ((((uint32_t)(kk * 2 + bcb[p])) ^ bxr[p]) << 4);
                LDSM_X4(bh, b);
                LDSM_X4(bl, b + (OFF_BLO - OFF_BHI));
#pragma unroll
                for (int mt = 0; mt < 2; mt++) {
                    MMA_F16(acc[mt][2 * p],     ah[mt][0], ah[mt][1], ah[mt][2], ah[mt][3], bh[0], bh[1]);
                    MMA_F16(acc[mt][2 * p + 1], ah[mt][0], ah[mt][1], ah[mt][2], ah[mt][3], bh[2], bh[3]);
                    MMA_F16(acc[mt][2 * p],     ah[mt][0], ah[mt][1], ah[mt][2], ah[mt][3], bl[0], bl[1]);
                    MMA_F16(acc[mt][2 * p + 1], ah[mt][0], ah[mt][1], ah[mt][2], ah[mt][3], bl[2], bl[3]);
                }
            }
        }
    }

    // ---- epilogue ----
    const int mrow = lane >> 2;
    const int cpair = (lane & 3) * 2;
#pragma unroll
    for (int mt = 0; mt < 2; mt++) {
#pragma unroll
        for (int rr = 0; rr < 2; rr++) {
            const int m = m0 + warp_m + mt * 16 + mrow + rr * 8;
            const int b = m >> 12;
            const int s = m & (Sc - 1);
#pragma unroll
            for (int nt = 0; nt < 8; nt++) {
                const int nl = warp_n + nt * 8 + cpair;
                float v0 = acc[mt][nt][rr * 2 + 0] + bias[n0 + nl];
                float v1 = acc[mt][nt][rr * 2 + 1] + bias[n0 + nl + 1];
                if (MODE == 1) {
                    const float cs = cosT[(size_t)s * Dc + nl];
                    const float sn = sinT[(size_t)s * Dc + nl];
                    const float e = v0 * cs - v1 * sn;
                    const float o_ = v1 * cs + v0 * sn;
                    v0 = fmaxf(e, 0.f);
                    v1 = fmaxf(o_, 0.f);
                }
                float2 w2 = make_float2(v0, v1);
                if (MODE == 0)
                    *(float2*)(out + (size_t)m * Cc + n0 + nl) = w2;
                else
                    *(float2*)(out + (((size_t)b * Hc + (n0 >> 7)) * Sc + s) * Dc + nl) = w2;
            }
        }
    }
}

// ======================= VK =======================
__global__ void __launch_bounds__(256) vk_kernel()
{
    const int bh = blockIdx.x;
    const int sp = blockIdx.y;
    const float* Vb = g_V + (size_t)bh * Sc * Dc;
    const float* Kb = g_K + (size_t)bh * Sc * Dc;

    __shared__ float Vs[16][128];
    __shared__ float Ks[16][128];

    const int tid = threadIdx.x;
    const int tx = tid & 15;
    const int ty = tid >> 4;
    const int lr = tid >> 5;
    const int lc = (tid & 31) * 4;

    float acc[8][8];
#pragma unroll
    for (int i = 0; i < 8; i++)
#pragma unroll
        for (int j = 0; j < 8; j++) acc[i][j] = 0.f;
    float csum = 0.f;

    const int schunk = Sc / NSPLIT;
    for (int st = 0; st < schunk / 16; st++) {
        const int s0 = sp * schunk + st * 16;
        __syncthreads();
        *(float4*)&Vs[lr][lc]     = *(const float4*)&Vb[(size_t)(s0 + lr) * Dc + lc];
        *(float4*)&Vs[lr + 8][lc] = *(const float4*)&Vb[(size_t)(s0 + lr + 8) * Dc + lc];
        *(float4*)&Ks[lr][lc]     = *(const float4*)&Kb[(size_t)(s0 + lr) * Dc + lc];
        *(float4*)&Ks[lr + 8][lc] = *(const float4*)&Kb[(size_t)(s0 + lr + 8) * Dc + lc];
        __syncthreads();
#pragma unroll
        for (int k = 0; k < 16; k++) {
            float4 a0 = *(const float4*)&Vs[k][ty * 8];
            float4 a1 = *(const float4*)&Vs[k][ty * 8 + 4];
            float4 b0 = *(const float4*)&Ks[k][tx * 8];
            float4 b1 = *(const float4*)&Ks[k][tx * 8 + 4];
            float av[8] = {a0.x, a0.y, a0.z, a0.w, a1.x, a1.y, a1.z, a1.w};
            float bv[8] = {b0.x, b0.y, b0.z, b0.w, b1.x, b1.y, b1.z, b1.w};
#pragma unroll
            for (int i = 0; i < 8; i++)
#pragma unroll
                for (int j = 0; j < 8; j++)
                    acc[i][j] = fmaf(av[i], bv[j], acc[i][j]);
        }
        if (tid < 128) {
#pragma unroll
            for (int k = 0; k < 16; k++) csum += Ks[k][tid];
        }
    }

    float* P = &g_VKpart[sp][(size_t)bh * 129 * Dc];
#pragma unroll
    for (int i = 0; i < 8; i++) {
        const int n = ty * 8 + i;
        *(float4*)&P[(size_t)n * Dc + tx * 8]     = make_float4(acc[i][0], acc[i][1], acc[i][2], acc[i][3]);
        *(float4*)&P[(size_t)n * Dc + tx * 8 + 4] = make_float4(acc[i][4], acc[i][5], acc[i][6], acc[i][7]);
    }
    if (tid < 128) P[(size_t)128 * Dc + tid] = csum;
}

__global__ void vk_reduce()
{
    const int i = blockIdx.x * 256 + threadIdx.x;
    if (i < Bc * Hc * 129 * Dc) {
        float s = 0.f;
#pragma unroll
        for (int p = 0; p < NSPLIT; p++) s += g_VKpart[p][i];
        g_VK[i] = s;
    }
}

// ------------- HS + divide; writes fp16 into ATT buffer -------------
__global__ void __launch_bounds__(256) attn_kernel()
{
    extern __shared__ float sm[];
    float* VKs = sm;
    float* Qs  = sm + 128 * 132;
    float* den = Qs + 128 * 132;

    const int bh = blockIdx.x;
    const int b = bh >> 4, h = bh & 15;
    const int s0 = blockIdx.y * 128;
    const int tid = threadIdx.x;
    const int tx = tid & 15;
    const int ty = tid >> 4;

    const float* VKg = g_VK + (size_t)bh * 129 * Dc;
    const float* Qg  = g_Q + ((size_t)bh * Sc + s0) * Dc;

    for (int idx = tid; idx < 129 * 128; idx += 256)
        VKs[(idx & 127) * 132 + (idx >> 7)] = VKg[idx];
    for (int idx = tid; idx < 128 * 128; idx += 256)
        Qs[(idx & 127) * 132 + (idx >> 7)] = Qg[idx];
    __syncthreads();

    float acc[8][8];
#pragma unroll
    for (int i = 0; i < 8; i++)
#pragma unroll
        for (int j = 0; j < 8; j++) acc[i][j] = 0.f;

#pragma unroll 4
    for (int k = 0; k < 128; k++) {
        float4 n0_ = *(const float4*)&VKs[k * 132 + ty * 8];
        float4 n1_ = *(const float4*)&VKs[k * 132 + ty * 8 + 4];
        float4 q0_ = *(const float4*)&Qs[k * 132 + tx * 8];
        float4 q1_ = *(const float4*)&Qs[k * 132 + tx * 8 + 4];
        float nv[8] = {n0_.x, n0_.y, n0_.z, n0_.w, n1_.x, n1_.y, n1_.z, n1_.w};
        float qv[8] = {q0_.x, q0_.y, q0_.z, q0_.w, q1_.x, q1_.y, q1_.z, q1_.w};
#pragma unroll
        for (int i = 0; i < 8; i++)
#pragma unroll
            for (int j = 0; j < 8; j++)
                acc[i][j] = fmaf(nv[i], qv[j], acc[i][j]);
    }

    if (tid < 128) {
        float d = 0.f;
#pragma unroll 4
        for (int k = 0; k < 128; k++)
            d = fmaf(VKs[k * 132 + 128], Qs[k * 132 + tid], d);
        den[tid] = d;
    }
    __syncthreads();

#pragma unroll
    for (int j = 0; j < 8; j++) {
        const int s = s0 + tx * 8 + j;
        const float inv = 1.0f / (den[tx * 8 + j] + 1e-15f);
        const size_t o = ((size_t)b * Sc + s) * Cc + h * Dc + ty * 8;
        *(uint4*)(g_AThi + o) = make_uint4(
            pack_h2(acc[0][j] * inv, acc[1][j] * inv),
            pack_h2(acc[2][j] * inv, acc[3][j] * inv),
            pack_h2(acc[4][j] * inv, acc[5][j] * inv),
            pack_h2(acc[6][j] * inv, acc[7][j] * inv));
    }
}

// ======================= launch =======================
extern "C" void kernel_launch(void* const* d_in, const int* in_sizes, int n_in,
                              void* d_out, int out_size)
{
    (void)in_sizes; (void)n_in; (void)out_size;
    const float* x    = (const float*)d_in[0];
    const float* cosT = (const float*)d_in[1];
    const float* sinT = (const float*)d_in[2];
    const float* Wq   = (const float*)d_in[3];
    const float* bq   = (const float*)d_in[4];
    const float* Wk   = (const float*)d_in[5];
    const float* bk   = (const float*)d_in[6];
    const float* Wv   = (const float*)d_in[7];
    const float* bv   = (const float*)d_in[8];
    const float* Wo   = (const float*)d_in[9];
    const float* bo   = (const float*)d_in[10];
    float* out = (float*)d_out;

    __half *xhi, *whi, *wlo, *athi;
    cudaGetSymbolAddress((void**)&xhi, g_Xhi);
    cudaGetSymbolAddress((void**)&whi, g_Whi);
    cudaGetSymbolAddress((void**)&wlo, g_Wlo);
    cudaGetSymbolAddress((void**)&athi, g_AThi);

    const size_t WSZ = (size_t)Cc * Cc;
    convert_hi<<<2048, 256>>>(x, xhi, (int)((size_t)Bc * Sc * Cc / 8));
    convert_hilo<<<1024, 256>>>(Wq, whi + 0 * WSZ, wlo + 0 * WSZ, (int)(WSZ / 8));
    convert_hilo<<<1024, 256>>>(Wk, whi + 1 * WSZ, wlo + 1 * WSZ, (int)(WSZ / 8));
    convert_hilo<<<1024, 256>>>(Wv, whi + 2 * WSZ, wlo + 2 * WSZ, (int)(WSZ / 8));
    convert_hilo<<<1024, 256>>>(Wo, whi + 3 * WSZ, wlo + 3 * WSZ, (int)(WSZ / 8));

    const int gsm = 4 * STAGE_BYTES;   // 131072
    cudaFuncSetAttribute(mma_gemm<0>, cudaFuncAttributeMaxDynamicSharedMemorySize, gsm);
    cudaFuncSetAttribute(mma_gemm<1>, cudaFuncAttributeMaxDynamicSharedMemorySize, gsm);
    cudaFuncSetAttribute(mma_gemm<2>, cudaFuncAttributeMaxDynamicSharedMemorySize, gsm);

    const dim3 gg(Cc / 128, (Bc * Sc) / 256);   // (16, 32)

    mma_gemm<1><<<gg, NT, gsm>>>(xhi, whi + 0 * WSZ, wlo + 0 * WSZ, bq, cosT, sinT, nullptr, 1);
    mma_gemm<1><<<gg, NT, gsm>>>(xhi, whi + 1 * WSZ, wlo + 1 * WSZ, bk, cosT, sinT, nullptr, 2);
    mma_gemm<2><<<gg, NT, gsm>>>(xhi, whi + 2 * WSZ, wlo + 2 * WSZ, bv, nullptr, nullptr, nullptr, 3);

    vk_kernel<<<dim3(Bc * Hc, NSPLIT), 256>>>();
    vk_reduce<<<(Bc * Hc * 129 * Dc + 255) / 256, 256>>>();

    const int smem = (128 * 132 * 2 + 128) * sizeof(float);
    cudaFuncSetAttribute(attn_kernel, cudaFuncAttributeMaxDynamicSharedMemorySize, smem);
    attn_kernel<<<dim3(Bc * Hc, Sc / 128), 256, smem>>>();

    mma_gemm<0><<<gg, NT, gsm>>>(athi, whi + 3 * WSZ, wlo + 3 * WSZ, bo, nullptr, nullptr, out, 0);
}

// round 7
// speedup vs baseline: 2.7962x; 1.0151x over previous
#include <cuda_runtime.h>
#include <cuda_fp16.h>
#include <cstdint>
#include <cstddef>

#define Bc 2
#define Sc 4096
#define Cc 2048
#define Hc 16
#define Dc 128
#define NSPLIT 8

// ---------------- scratch (device globals; no allocation) ----------------
__device__ float g_Q[(size_t)Bc * Hc * Sc * Dc];     // (b,h,s,d) fp32
__device__ float g_K[(size_t)Bc * Hc * Sc * Dc];
__device__ float g_V[(size_t)Bc * Hc * Sc * Dc];
__device__ float g_VKpart[NSPLIT][(size_t)Bc * Hc * 129 * Dc];
__device__ float g_VK[(size_t)Bc * Hc * 129 * Dc];
// fp16 operand buffers
__device__ __half g_Xhi[(size_t)Bc * Sc * Cc];
__device__ __half g_Whi[(size_t)4 * Cc * Cc];   // q,k,v,o
__device__ __half g_AThi[(size_t)Bc * Sc * Cc];

// ======================= helpers =======================
__device__ __forceinline__ uint32_t smem_u32(const void* p) {
    return (uint32_t)__cvta_generic_to_shared(p);
}
__device__ __forceinline__ uint32_t pack_h2(float x, float y) {
    __half2 h = __floats2half2_rn(x, y);
    return *reinterpret_cast<uint32_t*>(&h);
}
__device__ __forceinline__ void cpa16(uint32_t dst, const void* src) {
    asm volatile("cp.async.cg.shared.global [%0], [%1], 16;"
                 :: "r"(dst), "l"(__cvta_generic_to_global(src)) : "memory");
}
#define CP_COMMIT() asm volatile("cp.async.commit_group;" ::: "memory")
#define CP_WAIT2()  asm volatile("cp.async.wait_group 2;" ::: "memory")

#define LDSM_X4(r, addr) \
    asm volatile("ldmatrix.sync.aligned.m8n8.x4.shared.b16 {%0,%1,%2,%3}, [%4];" \
        : "=r"((r)[0]), "=r"((r)[1]), "=r"((r)[2]), "=r"((r)[3]) : "r"(addr))
#define MMA_F16(d, a0, a1, a2, a3, b0, b1) \
    asm volatile("mma.sync.aligned.m16n8k16.row.col.f32.f16.f16.f32 " \
        "{%0,%1,%2,%3}, {%4,%5,%6,%7}, {%8,%9}, {%0,%1,%2,%3};" \
        : "+f"((d)[0]), "+f"((d)[1]), "+f"((d)[2]), "+f"((d)[3]) \
        : "r"(a0), "r"(a1), "r"(a2), "r"(a3), "r"(b0), "r"(b1))

// ======================= fp32 -> fp16 converter =======================
__global__ void convert_hi(const float* __restrict__ src,
                           __half* __restrict__ hi, int n8)
{
    int i = blockIdx.x * blockDim.x + threadIdx.x;
    const int stride = gridDim.x * blockDim.x;
    for (; i < n8; i += stride) {
        float4 f0 = *(const float4*)(src + (size_t)i * 8);
        float4 f1 = *(const float4*)(src + (size_t)i * 8 + 4);
        *(uint4*)(hi + (size_t)i * 8) = make_uint4(
            pack_h2(f0.x, f0.y), pack_h2(f0.z, f0.w),
            pack_h2(f1.x, f1.y), pack_h2(f1.z, f1.w));
    }
}

// ======================= pipelined single-pass fp16 HMMA GEMM =======================
// C[m,n] = sum_k A[m,k] * W[n,k] + bias[n]
// CTA 256x128, K-chunk 32, 4 cp.async stages (24KB), 16 warps (8M x 2N), warp 32x64.
#define KCH 32
#define NCHUNK (Cc / KCH)          // 64
#define STAGE_BYTES 24576
#define OFF_BHI 16384
#define NT 512

template <int MODE>   // 0: row-major out; 1: RoPE+ReLU -> (b,h,s,d); 2: plain -> (b,h,s,d)
__global__ void __launch_bounds__(NT, 1) mma_gemm(
    const __half* __restrict__ Ahi,
    const __half* __restrict__ Bhi,
    const float* __restrict__ bias,
    const float* __restrict__ cosT, const float* __restrict__ sinT,
    float* __restrict__ dout, int out_sel)
{
    extern __shared__ __align__(16) char dyn[];
    float* out = (out_sel == 1) ? g_Q : (out_sel == 2) ? g_K
               : (out_sel == 3) ? g_V : dout;

    const int tid = threadIdx.x;
    const int lane = tid & 31;
    const int wid = tid >> 5;                 // 0..15
    const int m0 = blockIdx.y * 256;
    const int n0 = blockIdx.x * 128;
    const int warp_m = (wid >> 1) * 32;       // 8 m-groups
    const int warp_n = (wid & 1) * 64;        // 2 n-groups

    const uint32_t sb = smem_u32(dyn);

    // ---- cp.async dst offsets: A 2 chunks/thread, B 1 chunk/thread ----
    uint32_t dA[2], dB;
    {
        const int r = tid >> 1;                           // logical A row 0..255
        const uint32_t pr = (uint32_t)(r >> 1) * 128, xr = (r >> 1) & 7, r4 = (r & 1) * 4;
        const int cc0 = (tid & 1) * 2;
#pragma unroll
        for (int i = 0; i < 2; i++)
            dA[i] = pr + ((((uint32_t)(cc0 + i) + r4) ^ xr) << 4);
        const int rb = tid & 127;                          // logical B row
        const int ccb = tid >> 7;                          // chunk 0..3
        const uint32_t prb = (uint32_t)(rb >> 1) * 128, xb = (rb >> 1) & 7, rb4 = (rb & 1) * 4;
        dB = OFF_BHI + prb + ((((uint32_t)ccb + rb4) ^ xb) << 4);
    }
    const __half* aH = Ahi + (size_t)(m0 + (tid >> 1)) * Cc;
    const __half* bH = Bhi + (size_t)(n0 + (tid & 127)) * Cc;
    const int acc0 = (tid & 1) * 2;
    const int bccb = tid >> 7;

    // ---- ldmatrix address components ----
    uint32_t abase[2], axr[2];
    int acb[2];
#pragma unroll
    for (int mt = 0; mt < 2; mt++) {
        const int row = warp_m + mt * 16 + (lane & 15);
        abase[mt] = (uint32_t)(row >> 1) * 128;
        acb[mt] = (lane >> 4) + (row & 1) * 4;
        axr[mt] = (row >> 1) & 7;
    }
    uint32_t bbase[4], bxr[4];
    int bcb[4];
#pragma unroll
    for (int p = 0; p < 4; p++) {
        const int row = warp_n + p * 16 + ((lane >> 4) & 1) * 8 + (lane & 7);
        bbase[p] = OFF_BHI + (uint32_t)(row >> 1) * 128;
        bcb[p] = ((lane >> 3) & 1) + (row & 1) * 4;
        bxr[p] = (row >> 1) & 7;
    }

    float acc[2][8][4];
#pragma unroll
    for (int mt = 0; mt < 2; mt++)
#pragma unroll
        for (int nt = 0; nt < 8; nt++)
#pragma unroll
            for (int r = 0; r < 4; r++) acc[mt][nt][r] = 0.f;

    auto load_stage = [&](int buf, int kt) {
        const uint32_t st = sb + (uint32_t)buf * STAGE_BYTES;
        const int koff = kt * KCH;
#pragma unroll
        for (int i = 0; i < 2; i++)
            cpa16(st + dA[i], aH + koff + (acc0 + i) * 8);
        cpa16(st + dB, bH + koff + bccb * 8);
    };

#pragma unroll
    for (int s = 0; s < 3; s++) { load_stage(s, s); CP_COMMIT(); }

    for (int kt = 0; kt < NCHUNK; kt++) {
        CP_WAIT2();
        __syncthreads();
        if (kt + 3 < NCHUNK) load_stage((kt + 3) & 3, kt + 3);
        CP_COMMIT();

        const uint32_t st = sb + (uint32_t)(kt & 3) * STAGE_BYTES;
#pragma unroll
        for (int kk = 0; kk < 2; kk++) {
            uint32_t ah[2][4];
#pragma unroll
            for (int mt = 0; mt < 2; mt++) {
                const uint32_t a = st + abase[mt] +
                    ((((uint32_t)(kk * 2 + acb[mt])) ^ axr[mt]) << 4);
                LDSM_X4(ah[mt], a);
            }
#pragma unroll
            for (int p = 0; p < 4; p++) {
                uint32_t bh[4];
                const uint32_t b = st + bbase[p] +
                    ((((uint32_t)(kk * 2 + bcb[p])) ^ bxr[p]) << 4);
                LDSM_X4(bh, b);
#pragma unroll
                for (int mt = 0; mt < 2; mt++) {
                    MMA_F16(acc[mt][2 * p],     ah[mt][0], ah[mt][1], ah[mt][2], ah[mt][3], bh[0], bh[1]);
                    MMA_F16(acc[mt][2 * p + 1], ah[mt][0], ah[mt][1], ah[mt][2], ah[mt][3], bh[2], bh[3]);
                }
            }
        }
    }

    // ---- epilogue ----
    const int mrow = lane >> 2;
    const int cpair = (lane & 3) * 2;
#pragma unroll
    for (int mt = 0; mt < 2; mt++) {
#pragma unroll
        for (int rr = 0; rr < 2; rr++) {
            const int m = m0 + warp_m + mt * 16 + mrow + rr * 8;
            const int b = m >> 12;
            const int s = m & (Sc - 1);
#pragma unroll
            for (int nt = 0; nt < 8; nt++) {
                const int nl = warp_n + nt * 8 + cpair;
                float v0 = acc[mt][nt][rr * 2 + 0] + bias[n0 + nl];
                float v1 = acc[mt][nt][rr * 2 + 1] + bias[n0 + nl + 1];
                if (MODE == 1) {
                    const float cs = cosT[(size_t)s * Dc + nl];
                    const float sn = sinT[(size_t)s * Dc + nl];
                    const float e = v0 * cs - v1 * sn;
                    const float o_ = v1 * cs + v0 * sn;
                    v0 = fmaxf(e, 0.f);
                    v1 = fmaxf(o_, 0.f);
                }
                float2 w2 = make_float2(v0, v1);
                if (MODE == 0)
                    *(float2*)(out + (size_t)m * Cc + n0 + nl) = w2;
                else
                    *(float2*)(out + (((size_t)b * Hc + (n0 >> 7)) * Sc + s) * Dc + nl) = w2;
            }
        }
    }
}

// ======================= VK =======================
__global__ void __launch_bounds__(256) vk_kernel()
{
    const int bh = blockIdx.x;
    const int sp = blockIdx.y;
    const float* Vb = g_V + (size_t)bh * Sc * Dc;
    const float* Kb = g_K + (size_t)bh * Sc * Dc;

    __shared__ float Vs[16][128];
    __shared__ float Ks[16][128];

    const int tid = threadIdx.x;
    const int tx = tid & 15;
    const int ty = tid >> 4;
    const int lr = tid >> 5;
    const int lc = (tid & 31) * 4;

    float acc[8][8];
#pragma unroll
    for (int i = 0; i < 8; i++)
#pragma unroll
        for (int j = 0; j < 8; j++) acc[i][j] = 0.f;
    float csum = 0.f;

    const int schunk = Sc / NSPLIT;
    for (int st = 0; st < schunk / 16; st++) {
        const int s0 = sp * schunk + st * 16;
        __syncthreads();
        *(float4*)&Vs[lr][lc]     = *(const float4*)&Vb[(size_t)(s0 + lr) * Dc + lc];
        *(float4*)&Vs[lr + 8][lc] = *(const float4*)&Vb[(size_t)(s0 + lr + 8) * Dc + lc];
        *(float4*)&Ks[lr][lc]     = *(const float4*)&Kb[(size_t)(s0 + lr) * Dc + lc];
        *(float4*)&Ks[lr + 8][lc] = *(const float4*)&Kb[(size_t)(s0 + lr + 8) * Dc + lc];
        __syncthreads();
#pragma unroll
        for (int k = 0; k < 16; k++) {
            float4 a0 = *(const float4*)&Vs[k][ty * 8];
            float4 a1 = *(const float4*)&Vs[k][ty * 8 + 4];
            float4 b0 = *(const float4*)&Ks[k][tx * 8];
            float4 b1 = *(const float4*)&Ks[k][tx * 8 + 4];
            float av[8] = {a0.x, a0.y, a0.z, a0.w, a1.x, a1.y, a1.z, a1.w};
            float bv[8] = {b0.x, b0.y, b0.z, b0.w, b1.x, b1.y, b1.z, b1.w};
#pragma unroll
            for (int i = 0; i < 8; i++)
#pragma unroll
                for (int j = 0; j < 8; j++)
                    acc[i][j] = fmaf(av[i], bv[j], acc[i][j]);
        }
        if (tid < 128) {
#pragma unroll
            for (int k = 0; k < 16; k++) csum += Ks[k][tid];
        }
    }

    float* P = &g_VKpart[sp][(size_t)bh * 129 * Dc];
#pragma unroll
    for (int i = 0; i < 8; i++) {
        const int n = ty * 8 + i;
        *(float4*)&P[(size_t)n * Dc + tx * 8]     = make_float4(acc[i][0], acc[i][1], acc[i][2], acc[i][3]);
        *(float4*)&P[(size_t)n * Dc + tx * 8 + 4] = make_float4(acc[i][4], acc[i][5], acc[i][6], acc[i][7]);
    }
    if (tid < 128) P[(size_t)128 * Dc + tid] = csum;
}

__global__ void vk_reduce()
{
    const int i = blockIdx.x * 256 + threadIdx.x;
    if (i < Bc * Hc * 129 * Dc) {
        float s = 0.f;
#pragma unroll
        for (int p = 0; p < NSPLIT; p++) s += g_VKpart[p][i];
        g_VK[i] = s;
    }
}

// ------------- HS + divide; writes fp16 into ATT buffer -------------
__global__ void __launch_bounds__(256) attn_kernel()
{
    extern __shared__ float sm[];
    float* VKs = sm;
    float* Qs  = sm + 128 * 132;
    float* den = Qs + 128 * 132;

    const int bh = blockIdx.x;
    const int b = bh >> 4, h = bh & 15;
    const int s0 = blockIdx.y * 128;
    const int tid = threadIdx.x;
    const int tx = tid & 15;
    const int ty = tid >> 4;

    const float* VKg = g_VK + (size_t)bh * 129 * Dc;
    const float* Qg  = g_Q + ((size_t)bh * Sc + s0) * Dc;

    for (int idx = tid; idx < 129 * 128; idx += 256)
        VKs[(idx & 127) * 132 + (idx >> 7)] = VKg[idx];
    for (int idx = tid; idx < 128 * 128; idx += 256)
        Qs[(idx & 127) * 132 + (idx >> 7)] = Qg[idx];
    __syncthreads();

    float acc[8][8];
#pragma unroll
    for (int i = 0; i < 8; i++)
#pragma unroll
        for (int j = 0; j < 8; j++) acc[i][j] = 0.f;

#pragma unroll 4
    for (int k = 0; k < 128; k++) {
        float4 n0_ = *(const float4*)&VKs[k * 132 + ty * 8];
        float4 n1_ = *(const float4*)&VKs[k * 132 + ty * 8 + 4];
        float4 q0_ = *(const float4*)&Qs[k * 132 + tx * 8];
        float4 q1_ = *(const float4*)&Qs[k * 132 + tx * 8 + 4];
        float nv[8] = {n0_.x, n0_.y, n0_.z, n0_.w, n1_.x, n1_.y, n1_.z, n1_.w};
        float qv[8] = {q0_.x, q0_.y, q0_.z, q0_.w, q1_.x, q1_.y, q1_.z, q1_.w};
#pragma unroll
        for (int i = 0; i < 8; i++)
#pragma unroll
            for (int j = 0; j < 8; j++)
                acc[i][j] = fmaf(nv[i], qv[j], acc[i][j]);
    }

    if (tid < 128) {
        float d = 0.f;
#pragma unroll 4
        for (int k = 0; k < 128; k++)
            d = fmaf(VKs[k * 132 + 128], Qs[k * 132 + tid], d);
        den[tid] = d;
    }
    __syncthreads();

#pragma unroll
    for (int j = 0; j < 8; j++) {
        const int s = s0 + tx * 8 + j;
        const float inv = 1.0f / (den[tx * 8 + j] + 1e-15f);
        const size_t o = ((size_t)b * Sc + s) * Cc + h * Dc + ty * 8;
        *(uint4*)(g_AThi + o) = make_uint4(
            pack_h2(acc[0][j] * inv, acc[1][j] * inv),
            pack_h2(acc[2][j] * inv, acc[3][j] * inv),
            pack_h2(acc[4][j] * inv, acc[5][j] * inv),
            pack_h2(acc[6][j] * inv, acc[7][j] * inv));
    }
}

// ======================= launch =======================
extern "C" void kernel_launch(void* const* d_in, const int* in_sizes, int n_in,
                              void* d_out, int out_size)
{
    (void)in_sizes; (void)n_in; (void)out_size;
    const float* x    = (const float*)d_in[0];
    const float* cosT = (const float*)d_in[1];
    const float* sinT = (const float*)d_in[2];
    const float* Wq   = (const float*)d_in[3];
    const float* bq   = (const float*)d_in[4];
    const float* Wk   = (const float*)d_in[5];
    const float* bk   = (const float*)d_in[6];
    const float* Wv   = (const float*)d_in[7];
    const float* bv   = (const float*)d_in[8];
    const float* Wo   = (const float*)d_in[9];
    const float* bo   = (const float*)d_in[10];
    float* out = (float*)d_out;

    __half *xhi, *whi, *athi;
    cudaGetSymbolAddress((void**)&xhi, g_Xhi);
    cudaGetSymbolAddress((void**)&whi, g_Whi);
    cudaGetSymbolAddress((void**)&athi, g_AThi);

    const size_t WSZ = (size_t)Cc * Cc;
    convert_hi<<<2048, 256>>>(x, xhi, (int)((size_t)Bc * Sc * Cc / 8));
    convert_hi<<<1024, 256>>>(Wq, whi + 0 * WSZ, (int)(WSZ / 8));
    convert_hi<<<1024, 256>>>(Wk, whi + 1 * WSZ, (int)(WSZ / 8));
    convert_hi<<<1024, 256>>>(Wv, whi + 2 * WSZ, (int)(WSZ / 8));
    convert_hi<<<1024, 256>>>(Wo, whi + 3 * WSZ, (int)(WSZ / 8));

    const int gsm = 4 * STAGE_BYTES;   // 98304
    cudaFuncSetAttribute(mma_gemm<0>, cudaFuncAttributeMaxDynamicSharedMemorySize, gsm);
    cudaFuncSetAttribute(mma_gemm<1>, cudaFuncAttributeMaxDynamicSharedMemorySize, gsm);
    cudaFuncSetAttribute(mma_gemm<2>, cudaFuncAttributeMaxDynamicSharedMemorySize, gsm);

    const dim3 gg(Cc / 128, (Bc * Sc) / 256);   // (16, 32)

    mma_gemm<1><<<gg, NT, gsm>>>(xhi, whi + 0 * WSZ, bq, cosT, sinT, nullptr, 1);
    mma_gemm<1><<<gg, NT, gsm>>>(xhi, whi + 1 * WSZ, bk, cosT, sinT, nullptr, 2);
    mma_gemm<2><<<gg, NT, gsm>>>(xhi, whi + 2 * WSZ, bv, nullptr, nullptr, nullptr, 3);

    vk_kernel<<<dim3(Bc * Hc, NSPLIT), 256>>>();
    vk_reduce<<<(Bc * Hc * 129 * Dc + 255) / 256, 256>>>();

    const int smem = (128 * 132 * 2 + 128) * sizeof(float);
    cudaFuncSetAttribute(attn_kernel, cudaFuncAttributeMaxDynamicSharedMemorySize, smem);
    attn_kernel<<<dim3(Bc * Hc, Sc / 128), 256, smem>>>();

    mma_gemm<0><<<gg, NT, gsm>>>(athi, whi + 3 * WSZ, bo, nullptr, nullptr, out, 0);
}

// round 9
// speedup vs baseline: 5.0700x; 1.8131x over previous
#include <cuda_runtime.h>
#include <cuda_fp16.h>
#include <cstdint>
#include <cstddef>

#define Bc 2
#define Sc 4096
#define Cc 2048
#define Hc 16
#define Dc 128
#define NSPLIT 8

// ---------------- scratch (device globals; no allocation) ----------------
__device__ float g_K[(size_t)Bc * Hc * Sc * Dc];     // fp32 (b,h,s,d)
__device__ float g_V[(size_t)Bc * Hc * Sc * Dc];
__device__ float g_VKpart[NSPLIT][(size_t)Bc * Hc * 129 * Dc];
__device__ __half g_Qh[(size_t)Bc * Hc * Sc * Dc];   // fp16 (b,h,s,d)
__device__ __half g_VKh[(size_t)Bc * Hc * 129 * Dc]; // fp16
__device__ __half g_Xhi[(size_t)Bc * Sc * Cc];
__device__ __half g_Whi[(size_t)4 * Cc * Cc];        // q,k,v,o contiguous
__device__ __half g_AThi[(size_t)Bc * Sc * Cc];

// ======================= helpers =======================
__device__ __forceinline__ uint32_t smem_u32(const void* p) {
    return (uint32_t)__cvta_generic_to_shared(p);
}
__device__ __forceinline__ uint32_t pack_h2(float x, float y) {
    __half2 h = __floats2half2_rn(x, y);
    return *reinterpret_cast<uint32_t*>(&h);
}
__device__ __forceinline__ void cpa16(uint32_t dst, const void* src) {
    asm volatile("cp.async.cg.shared.global [%0], [%1], 16;"
                 :: "r"(dst), "l"(__cvta_generic_to_global(src)) : "memory");
}
#define CP_COMMIT() asm volatile("cp.async.commit_group;" ::: "memory")
#define CP_WAIT2()  asm volatile("cp.async.wait_group 2;" ::: "memory")

#define LDSM_X4(r, addr) \
    asm volatile("ldmatrix.sync.aligned.m8n8.x4.shared.b16 {%0,%1,%2,%3}, [%4];" \
        : "=r"((r)[0]), "=r"((r)[1]), "=r"((r)[2]), "=r"((r)[3]) : "r"(addr))
#define MMA_F16(d, a0, a1, a2, a3, b0, b1) \
    asm volatile("mma.sync.aligned.m16n8k16.row.col.f32.f16.f16.f32 " \
        "{%0,%1,%2,%3}, {%4,%5,%6,%7}, {%8,%9}, {%0,%1,%2,%3};" \
        : "+f"((d)[0]), "+f"((d)[1]), "+f"((d)[2]), "+f"((d)[3]) \
        : "r"(a0), "r"(a1), "r"(a2), "r"(a3), "r"(b0), "r"(b1))

// ======================= fp32 -> fp16 converter =======================
__global__ void convert_hi(const float* __restrict__ src,
                           __half* __restrict__ hi, int n8)
{
    int i = blockIdx.x * blockDim.x + threadIdx.x;
    const int stride = gridDim.x * blockDim.x;
    for (; i < n8; i += stride) {
        float4 f0 = *(const float4*)(src + (size_t)i * 8);
        float4 f1 = *(const float4*)(src + (size_t)i * 8 + 4);
        *(uint4*)(hi + (size_t)i * 8) = make_uint4(
            pack_h2(f0.x, f0.y), pack_h2(f0.z, f0.w),
            pack_h2(f1.x, f1.y), pack_h2(f1.z, f1.w));
    }
}

// ======================= fp16 HMMA GEMM (proven R7 geometry) =======================
// CTA 256x128, K-chunk 32, 4 cp.async stages (24KB), 16 warps (8M x 2N), warp 32x64.
// QKV=1: N spans Wq|Wk|Wv (6144). Q -> fp16 g_Qh (RoPE+ReLU), K -> fp32 g_K
// (RoPE+ReLU), V -> fp32 g_V. QKV=0: plain row-major fp32 out + bias b0.
#define KCH 32
#define NCHUNK (Cc / KCH)          // 64
#define STAGE_BYTES 24576
#define OFF_BHI 16384
#define NT 512

template <int QKV>
__global__ void __launch_bounds__(NT, 1) mma_gemm(
    const __half* __restrict__ Ah, const __half* __restrict__ Bh,
    const float* __restrict__ b0, const float* __restrict__ b1,
    const float* __restrict__ b2,
    const float* __restrict__ cosT, const float* __restrict__ sinT,
    float* __restrict__ dout)
{
    extern __shared__ __align__(16) char dyn[];

    const int tid = threadIdx.x;
    const int lane = tid & 31;
    const int wid = tid >> 5;                 // 0..15
    const int m0 = blockIdx.y * 256;
    const int n0 = blockIdx.x * 128;
    const int warp_m = (wid >> 1) * 32;       // 8 m-groups
    const int warp_n = (wid & 1) * 64;        // 2 n-groups

    const uint32_t sb = smem_u32(dyn);

    // ---- cp.async dst offsets: A 2 chunks/thread, B 1 chunk/thread ----
    uint32_t dA[2], dB;
    {
        const int r = tid >> 1;                           // logical A row 0..255
        const uint32_t pr = (uint32_t)(r >> 1) * 128, xr = (r >> 1) & 7, r4 = (r & 1) * 4;
        const int cc0 = (tid & 1) * 2;
#pragma unroll
        for (int i = 0; i < 2; i++)
            dA[i] = pr + ((((uint32_t)(cc0 + i) + r4) ^ xr) << 4);
        const int rb = tid & 127;                          // logical B row
        const int ccb = tid >> 7;                          // chunk 0..3
        const uint32_t prb = (uint32_t)(rb >> 1) * 128, xb = (rb >> 1) & 7, rb4 = (rb & 1) * 4;
        dB = OFF_BHI + prb + ((((uint32_t)ccb + rb4) ^ xb) << 4);
    }
    const __half* aP = Ah + (size_t)(m0 + (tid >> 1)) * Cc;
    const __half* bP = Bh + (size_t)(n0 + (tid & 127)) * Cc;
    const int acc0 = (tid & 1) * 2;
    const int bccb = tid >> 7;

    // ---- ldmatrix address components ----
    uint32_t abase[2], axr[2];
    int acb[2];
#pragma unroll
    for (int mt = 0; mt < 2; mt++) {
        const int row = warp_m + mt * 16 + (lane & 15);
        abase[mt] = (uint32_t)(row >> 1) * 128;
        acb[mt] = (lane >> 4) + (row & 1) * 4;
        axr[mt] = (row >> 1) & 7;
    }
    uint32_t bbase[4], bxr[4];
    int bcb[4];
#pragma unroll
    for (int p = 0; p < 4; p++) {
        const int row = warp_n + p * 16 + ((lane >> 4) & 1) * 8 + (lane & 7);
        bbase[p] = OFF_BHI + (uint32_t)(row >> 1) * 128;
        bcb[p] = ((lane >> 3) & 1) + (row & 1) * 4;
        bxr[p] = (row >> 1) & 7;
    }

    float acc[2][8][4];
#pragma unroll
    for (int mt = 0; mt < 2; mt++)
#pragma unroll
        for (int nt = 0; nt < 8; nt++)
#pragma unroll
            for (int r = 0; r < 4; r++) acc[mt][nt][r] = 0.f;

    auto load_stage = [&](int buf, int kt) {
        const uint32_t st = sb + (uint32_t)buf * STAGE_BYTES;
        const int koff = kt * KCH;
#pragma unroll
        for (int i = 0; i < 2; i++)
            cpa16(st + dA[i], aP + koff + (acc0 + i) * 8);
        cpa16(st + dB, bP + koff + bccb * 8);
    };

#pragma unroll
    for (int s = 0; s < 3; s++) { load_stage(s, s); CP_COMMIT(); }

    for (int kt = 0; kt < NCHUNK; kt++) {
        CP_WAIT2();
        __syncthreads();
        if (kt + 3 < NCHUNK) load_stage((kt + 3) & 3, kt + 3);
        CP_COMMIT();

        const uint32_t st = sb + (uint32_t)(kt & 3) * STAGE_BYTES;
#pragma unroll
        for (int kk = 0; kk < 2; kk++) {
            uint32_t ah[2][4];
#pragma unroll
            for (int mt = 0; mt < 2; mt++) {
                const uint32_t a = st + abase[mt] +
                    ((((uint32_t)(kk * 2 + acb[mt])) ^ axr[mt]) << 4);
                LDSM_X4(ah[mt], a);
            }
#pragma unroll
            for (int p = 0; p < 4; p++) {
                uint32_t bh[4];
                const uint32_t b = st + bbase[p] +
                    ((((uint32_t)(kk * 2 + bcb[p])) ^ bxr[p]) << 4);
                LDSM_X4(bh, b);
#pragma unroll
                for (int mt = 0; mt < 2; mt++) {
                    MMA_F16(acc[mt][2 * p],     ah[mt][0], ah[mt][1], ah[mt][2], ah[mt][3], bh[0], bh[1]);
                    MMA_F16(acc[mt][2 * p + 1], ah[mt][0], ah[mt][1], ah[mt][2], ah[mt][3], bh[2], bh[3]);
                }
            }
        }
    }

    // ---- epilogue ----
    const int mrow = lane >> 2;
    const int cpair = (lane & 3) * 2;
    const int which = QKV ? (n0 >> 11) : 0;      // uniform per CTA
    const int nseg = QKV ? (n0 & 2047) : n0;
    const int h = nseg >> 7;
    const float* bp = QKV ? (which == 0 ? b0 : which == 1 ? b1 : b2) : b0;

#pragma unroll
    for (int mt = 0; mt < 2; mt++) {
#pragma unroll
        for (int rr = 0; rr < 2; rr++) {
            const int m = m0 + warp_m + mt * 16 + mrow + rr * 8;
            const int b = m >> 12;
            const int s = m & (Sc - 1);
#pragma unroll
            for (int nt = 0; nt < 8; nt++) {
                const int nl = warp_n + nt * 8 + cpair;     // 0..127
                float v0 = acc[mt][nt][rr * 2 + 0] + bp[nseg + nl];
                float v1 = acc[mt][nt][rr * 2 + 1] + bp[nseg + nl + 1];
                if (QKV) {
                    if (which < 2) {
                        const float cs = cosT[(size_t)s * Dc + nl];
                        const float sn = sinT[(size_t)s * Dc + nl];
                        const float e = v0 * cs - v1 * sn;
                        const float o_ = v1 * cs + v0 * sn;
                        v0 = fmaxf(e, 0.f);
                        v1 = fmaxf(o_, 0.f);
                    }
                    const size_t oi = (((size_t)b * Hc + h) * Sc + s) * Dc + nl;
                    if (which == 0)
                        *(uint32_t*)(g_Qh + oi) = pack_h2(v0, v1);
                    else if (which == 1)
                        *(float2*)(g_K + oi) = make_float2(v0, v1);
                    else
                        *(float2*)(g_V + oi) = make_float2(v0, v1);
                } else {
                    *(float2*)(dout + (size_t)m * Cc + nseg + nl) = make_float2(v0, v1);
                }
            }
        }
    }
}

// ======================= VK (fp32, unchanged) =======================
__global__ void __launch_bounds__(256) vk_kernel()
{
    const int bh = blockIdx.x;
    const int sp = blockIdx.y;
    const float* Vb = g_V + (size_t)bh * Sc * Dc;
    const float* Kb = g_K + (size_t)bh * Sc * Dc;

    __shared__ float Vs[16][128];
    __shared__ float Ks[16][128];

    const int tid = threadIdx.x;
    const int tx = tid & 15;
    const int ty = tid >> 4;
    const int lr = tid >> 5;
    const int lc = (tid & 31) * 4;

    float acc[8][8];
#pragma unroll
    for (int i = 0; i < 8; i++)
#pragma unroll
        for (int j = 0; j < 8; j++) acc[i][j] = 0.f;
    float csum = 0.f;

    const int schunk = Sc / NSPLIT;
    for (int st = 0; st < schunk / 16; st++) {
        const int s0 = sp * schunk + st * 16;
        __syncthreads();
        *(float4*)&Vs[lr][lc]     = *(const float4*)&Vb[(size_t)(s0 + lr) * Dc + lc];
        *(float4*)&Vs[lr + 8][lc] = *(const float4*)&Vb[(size_t)(s0 + lr + 8) * Dc + lc];
        *(float4*)&Ks[lr][lc]     = *(const float4*)&Kb[(size_t)(s0 + lr) * Dc + lc];
        *(float4*)&Ks[lr + 8][lc] = *(const float4*)&Kb[(size_t)(s0 + lr + 8) * Dc + lc];
        __syncthreads();
#pragma unroll
        for (int k = 0; k < 16; k++) {
            float4 a0 = *(const float4*)&Vs[k][ty * 8];
            float4 a1 = *(const float4*)&Vs[k][ty * 8 + 4];
            float4 b0 = *(const float4*)&Ks[k][tx * 8];
            float4 b1 = *(const float4*)&Ks[k][tx * 8 + 4];
            float av[8] = {a0.x, a0.y, a0.z, a0.w, a1.x, a1.y, a1.z, a1.w};
            float bv[8] = {b0.x, b0.y, b0.z, b0.w, b1.x, b1.y, b1.z, b1.w};
#pragma unroll
            for (int i = 0; i < 8; i++)
#pragma unroll
                for (int j = 0; j < 8; j++)
                    acc[i][j] = fmaf(av[i], bv[j], acc[i][j]);
        }
        if (tid < 128) {
#pragma unroll
            for (int k = 0; k < 16; k++) csum += Ks[k][tid];
        }
    }

    float* P = &g_VKpart[sp][(size_t)bh * 129 * Dc];
#pragma unroll
    for (int i = 0; i < 8; i++) {
        const int n = ty * 8 + i;
        *(float4*)&P[(size_t)n * Dc + tx * 8]     = make_float4(acc[i][0], acc[i][1], acc[i][2], acc[i][3]);
        *(float4*)&P[(size_t)n * Dc + tx * 8 + 4] = make_float4(acc[i][4], acc[i][5], acc[i][6], acc[i][7]);
    }
    if (tid < 128) P[(size_t)128 * Dc + tid] = csum;
}

__global__ void vk_reduce()
{
    const int i = blockIdx.x * 256 + threadIdx.x;
    if (i < Bc * Hc * 129 * Dc) {
        float s = 0.f;
#pragma unroll
        for (int p = 0; p < NSPLIT; p++) s += g_VKpart[p][i];
        g_VKh[i] = __float2half(s);
    }
}

// ======================= fp16 HMMA attn: hs[s,n] = (Q . VK) / den =======================
// Per block (bh, s-block-128): Q 128x128 fp16, VK 129x128 fp16 in smem (row
// stride 272B -> conflict-free ldmatrix). 8 warps (4s x 2n), warp tile 32x64.
#define QROW 272
#define SM_VK 34816                 // 128*272
#define SM_DEN (34816 + 35088)      // + 129*272

__global__ void __launch_bounds__(256) attn_mma()
{
    extern __shared__ __align__(16) char sm[];
    float* den = (float*)(sm + SM_DEN);

    const int bh = blockIdx.x;
    const int b = bh >> 4, h = bh & 15;
    const int s0 = blockIdx.y * 128;
    const int tid = threadIdx.x;
    const int lane = tid & 31;
    const int wid = tid >> 5;
    const int warp_m = (wid >> 1) * 32;   // s dim
    const int warp_n = (wid & 1) * 64;    // n dim

    const uint32_t sb = smem_u32(sm);

    // ---- load Q (128x128) and VK (129x128) fp16 tiles ----
    const __half* Qg = g_Qh + ((size_t)bh * Sc + s0) * Dc;
    for (int idx = tid; idx < 128 * 16; idx += 256) {
        const int r = idx >> 4, c = idx & 15;
        *(uint4*)(sm + r * QROW + c * 16) = *(const uint4*)(Qg + (size_t)r * Dc + c * 8);
    }
    const __half* VKg = g_VKh + (size_t)bh * 129 * Dc;
    for (int idx = tid; idx < 129 * 16; idx += 256) {
        const int r = idx >> 4, c = idx & 15;
        *(uint4*)(sm + SM_VK + r * QROW + c * 16) = *(const uint4*)(VKg + (size_t)r * Dc + c * 8);
    }
    __syncthreads();

    float acc[2][8][4];
#pragma unroll
    for (int mt = 0; mt < 2; mt++)
#pragma unroll
        for (int nt = 0; nt < 8; nt++)
#pragma unroll
            for (int r = 0; r < 4; r++) acc[mt][nt][r] = 0.f;

    uint32_t a_addr[2];
#pragma unroll
    for (int mt = 0; mt < 2; mt++)
        a_addr[mt] = sb + (warp_m + mt * 16 + (lane & 15)) * QROW + (lane >> 4) * 16;
    uint32_t b_addr[4];
#pragma unroll
    for (int p = 0; p < 4; p++)
        b_addr[p] = sb + SM_VK +
            (warp_n + p * 16 + ((lane >> 4) & 1) * 8 + (lane & 7)) * QROW +
            ((lane >> 3) & 1) * 16;

#pragma unroll
    for (int ks = 0; ks < 8; ks++) {
        uint32_t ah[2][4];
        LDSM_X4(ah[0], a_addr[0] + ks * 32);
        LDSM_X4(ah[1], a_addr[1] + ks * 32);
#pragma unroll
        for (int p = 0; p < 4; p++) {
            uint32_t bhreg[4];
            LDSM_X4(bhreg, b_addr[p] + ks * 32);
#pragma unroll
            for (int mt = 0; mt < 2; mt++) {
                MMA_F16(acc[mt][2 * p],     ah[mt][0], ah[mt][1], ah[mt][2], ah[mt][3], bhreg[0], bhreg[1]);
                MMA_F16(acc[mt][2 * p + 1], ah[mt][0], ah[mt][1], ah[mt][2], ah[mt][3], bhreg[2], bhreg[3]);
            }
        }
    }

    // ---- denominator: den[s] = 1 / (VK[128,:] . Q[s,:] + eps) ----
    if (tid < 128) {
        const __half2* vrow = (const __half2*)(sm + SM_VK + 128 * QROW);
        const __half2* qrow = (const __half2*)(sm + tid * QROW);
        float d = 0.f;
#pragma unroll 8
        for (int i = 0; i < 64; i++) {
            const float2 v = __half22float2(vrow[i]);
            const float2 q = __half22float2(qrow[i]);
            d = fmaf(v.x, q.x, d);
            d = fmaf(v.y, q.y, d);
        }
        den[tid] = 1.0f / (d + 1e-15f);
    }
    __syncthreads();

    // ---- epilogue: divide + fp16 pack -> g_AThi (b, s, h*128+n) ----
    const int mrow = lane >> 2;
    const int cpair = (lane & 3) * 2;
#pragma unroll
    for (int mt = 0; mt < 2; mt++) {
#pragma unroll
        for (int rr = 0; rr < 2; rr++) {
            const int m = warp_m + mt * 16 + mrow + rr * 8;    // s-local
            const float inv = den[m];
            __half* op = g_AThi + ((size_t)b * Sc + s0 + m) * Cc + h * Dc;
#pragma unroll
            for (int nt = 0; nt < 8; nt++) {
                const int n = warp_n + nt * 8 + cpair;
                *(uint32_t*)(op + n) =
                    pack_h2(acc[mt][nt][rr * 2] * inv, acc[mt][nt][rr * 2 + 1] * inv);
            }
        }
    }
}

// ======================= launch =======================
extern "C" void kernel_launch(void* const* d_in, const int* in_sizes, int n_in,
                              void* d_out, int out_size)
{
    (void)in_sizes; (void)n_in; (void)out_size;
    const float* x    = (const float*)d_in[0];
    const float* cosT = (const float*)d_in[1];
    const float* sinT = (const float*)d_in[2];
    const float* Wq   = (const float*)d_in[3];
    const float* bq   = (const float*)d_in[4];
    const float* Wk   = (const float*)d_in[5];
    const float* bk   = (const float*)d_in[6];
    const float* Wv   = (const float*)d_in[7];
    const float* bv   = (const float*)d_in[8];
    const float* Wo   = (const float*)d_in[9];
    const float* bo   = (const float*)d_in[10];
    float* out = (float*)d_out;

    __half *xhi, *whi, *athi;
    cudaGetSymbolAddress((void**)&xhi, g_Xhi);
    cudaGetSymbolAddress((void**)&whi, g_Whi);
    cudaGetSymbolAddress((void**)&athi, g_AThi);

    const size_t WSZ = (size_t)Cc * Cc;
    convert_hi<<<2048, 256>>>(x, xhi, (int)((size_t)Bc * Sc * Cc / 8));
    convert_hi<<<1024, 256>>>(Wq, whi + 0 * WSZ, (int)(WSZ / 8));
    convert_hi<<<1024, 256>>>(Wk, whi + 1 * WSZ, (int)(WSZ / 8));
    convert_hi<<<1024, 256>>>(Wv, whi + 2 * WSZ, (int)(WSZ / 8));
    convert_hi<<<1024, 256>>>(Wo, whi + 3 * WSZ, (int)(WSZ / 8));

    const int gsm = 4 * STAGE_BYTES;   // 98304
    cudaFuncSetAttribute(mma_gemm<0>, cudaFuncAttributeMaxDynamicSharedMemorySize, gsm);
    cudaFuncSetAttribute(mma_gemm<1>, cudaFuncAttributeMaxDynamicSharedMemorySize, gsm);

    // merged QKV: N = 6144, grid (48, 32)
    mma_gemm<1><<<dim3(48, 32), NT, gsm>>>(xhi, whi, bq, bk, bv, cosT, sinT, nullptr);

    vk_kernel<<<dim3(Bc * Hc, NSPLIT), 256>>>();
    vk_reduce<<<(Bc * Hc * 129 * Dc + 255) / 256, 256>>>();

    const int asm_ = SM_DEN + 128 * sizeof(float) + 16;   // ~70.4KB
    cudaFuncSetAttribute(attn_mma, cudaFuncAttributeMaxDynamicSharedMemorySize, asm_);
    attn_mma<<<dim3(Bc * Hc, Sc / 128), 256, asm_>>>();

    // O projection
    mma_gemm<0><<<dim3(16, 32), NT, gsm>>>(athi, whi + 3 * WSZ, bo, bo, bo,
                                           nullptr, nullptr, out);
}

// round 10
// speedup vs baseline: 6.4109x; 1.2645x over previous
#include <cuda_runtime.h>
#include <cuda_fp16.h>
#include <cstdint>
#include <cstddef>

#define Bc 2
#define Sc 4096
#define Cc 2048
#define Hc 16
#define Dc 128
#define NSPLIT 8

// ---------------- scratch (device globals; no allocation) ----------------
__device__ float g_K[(size_t)Bc * Hc * Sc * Dc];     // fp32 (b,h,s,d)
__device__ float g_V[(size_t)Bc * Hc * Sc * Dc];
__device__ float g_VKpart[NSPLIT][(size_t)Bc * Hc * 129 * Dc];
__device__ __half g_Qh[(size_t)Bc * Hc * Sc * Dc];   // fp16 (b,h,s,d)
__device__ __half g_VKh[(size_t)Bc * Hc * 129 * Dc]; // fp16
__device__ __half g_Xhi[(size_t)Bc * Sc * Cc];
__device__ __half g_Whi[(size_t)4 * Cc * Cc];        // q,k,v,o contiguous
__device__ __half g_AThi[(size_t)Bc * Sc * Cc];

// ======================= helpers =======================
__device__ __forceinline__ uint32_t smem_u32(const void* p) {
    return (uint32_t)__cvta_generic_to_shared(p);
}
__device__ __forceinline__ uint32_t pack_h2(float x, float y) {
    __half2 h = __floats2half2_rn(x, y);
    return *reinterpret_cast<uint32_t*>(&h);
}
__device__ __forceinline__ void mbar_init(uint32_t a, uint32_t cnt) {
    asm volatile("mbarrier.init.shared.b64 [%0], %1;" :: "r"(a), "r"(cnt) : "memory");
}
__device__ __forceinline__ void mbar_expect_tx(uint32_t a, uint32_t bytes) {
    asm volatile("mbarrier.arrive.expect_tx.shared.b64 _, [%0], %1;"
                 :: "r"(a), "r"(bytes) : "memory");
}
__device__ __forceinline__ void mbar_wait(uint32_t a, uint32_t parity) {
    uint32_t done = 0;
    while (!done) {
        asm volatile(
            "{\n\t.reg .pred p;\n\t"
            "mbarrier.try_wait.parity.acquire.cta.shared::cta.b64 p, [%1], %2, 0x989680;\n\t"
            "selp.b32 %0, 1, 0, p;\n\t}"
            : "=r"(done) : "r"(a), "r"(parity) : "memory");
    }
}
__device__ __forceinline__ void bulk_g2s(uint32_t dst, const void* src,
                                         uint32_t bytes, uint32_t mbar) {
    asm volatile(
        "cp.async.bulk.shared::cluster.global.mbarrier::complete_tx::bytes "
        "[%0], [%1], %2, [%3];"
        :: "r"(dst), "l"(__cvta_generic_to_global(src)), "r"(bytes), "r"(mbar)
        : "memory");
}

#define LDSM_X4(r, addr) \
    asm volatile("ldmatrix.sync.aligned.m8n8.x4.shared.b16 {%0,%1,%2,%3}, [%4];" \
        : "=r"((r)[0]), "=r"((r)[1]), "=r"((r)[2]), "=r"((r)[3]) : "r"(addr))
#define MMA_F16(d, a0, a1, a2, a3, b0, b1) \
    asm volatile("mma.sync.aligned.m16n8k16.row.col.f32.f16.f16.f32 " \
        "{%0,%1,%2,%3}, {%4,%5,%6,%7}, {%8,%9}, {%0,%1,%2,%3};" \
        : "+f"((d)[0]), "+f"((d)[1]), "+f"((d)[2]), "+f"((d)[3]) \
        : "r"(a0), "r"(a1), "r"(a2), "r"(a3), "r"(b0), "r"(b1))

// ======================= fp32 -> fp16 converter =======================
__global__ void convert_hi(const float* __restrict__ src,
                           __half* __restrict__ hi, int n8)
{
    int i = blockIdx.x * blockDim.x + threadIdx.x;
    const int stride = gridDim.x * blockDim.x;
    for (; i < n8; i += stride) {
        float4 f0 = *(const float4*)(src + (size_t)i * 8);
        float4 f1 = *(const float4*)(src + (size_t)i * 8 + 4);
        *(uint4*)(hi + (size_t)i * 8) = make_uint4(
            pack_h2(f0.x, f0.y), pack_h2(f0.z, f0.w),
            pack_h2(f1.x, f1.y), pack_h2(f1.z, f1.w));
    }
}

// ======================= fp16 HMMA GEMM, cp.async.bulk loads =======================
// CTA 256x128, K-chunk 128 (one 256B bulk op per row), 2 stages, 16 warps
// (8M x 2N), warp 32x64. Rows padded to 272B -> conflict-free ldmatrix.
// QKV=1: N spans Wq|Wk|Wv (6144). Q->fp16 g_Qh (RoPE+ReLU), K->fp32 g_K
// (RoPE+ReLU), V->fp32 g_V. QKV=0: plain row-major fp32 out + bias b0.
#define KCH 128
#define NCHUNK (Cc / KCH)          // 16
#define ROWB 272
#define OFFB (256 * ROWB)          // 69632
#define STAGEB (OFFB + 128 * ROWB) // 104448
#define TXBYTES (384 * 256)        // 98304
#define NT 512

template <int QKV>
__global__ void __launch_bounds__(NT, 1) mma_gemm(
    const __half* __restrict__ Ah, const __half* __restrict__ Bh,
    const float* __restrict__ b0, const float* __restrict__ b1,
    const float* __restrict__ b2,
    const float* __restrict__ cosT, const float* __restrict__ sinT,
    float* __restrict__ dout)
{
    extern __shared__ __align__(16) char dyn[];
    __shared__ __align__(8) uint64_t mbar_store[2];

    const int tid = threadIdx.x;
    const int lane = tid & 31;
    const int wid = tid >> 5;                 // 0..15
    const int m0 = blockIdx.y * 256;
    const int n0 = blockIdx.x * 128;
    const int warp_m = (wid >> 1) * 32;       // 8 m-groups
    const int warp_n = (wid & 1) * 64;        // 2 n-groups

    const uint32_t sb = smem_u32(dyn);
    const uint32_t mb0 = smem_u32(&mbar_store[0]);
    const uint32_t mb1 = smem_u32(&mbar_store[1]);

    if (tid == 0) { mbar_init(mb0, 1); mbar_init(mb1, 1); }
    __syncthreads();

    // ---- per-thread bulk-load row assignment ----
    const bool isA = tid < 256;
    const bool isB = (tid >= 256) && (tid < 384);
    const __half* srcRow = isA ? (Ah + (size_t)(m0 + tid) * Cc)
                    : (isB ? (Bh + (size_t)(n0 + tid - 256) * Cc) : nullptr);
    const uint32_t dstRow = isA ? (uint32_t)tid * ROWB
                    : (isB ? OFFB + (uint32_t)(tid - 256) * ROWB : 0u);

    auto load_chunk = [&](int kt) {
        const uint32_t st = sb + (uint32_t)(kt & 1) * STAGEB;
        const uint32_t bar = (kt & 1) ? mb1 : mb0;
        if (tid == 0) mbar_expect_tx(bar, TXBYTES);
        if (srcRow) bulk_g2s(st + dstRow, srcRow + (size_t)kt * KCH, 256, bar);
    };

    // ---- ldmatrix offsets (stage-relative, linear 272B rows) ----
    uint32_t a_off[2];
#pragma unroll
    for (int mt = 0; mt < 2; mt++)
        a_off[mt] = (uint32_t)(warp_m + mt * 16 + (lane & 15)) * ROWB + (lane >> 4) * 16;
    uint32_t b_off[4];
#pragma unroll
    for (int p = 0; p < 4; p++)
        b_off[p] = OFFB +
            (uint32_t)(warp_n + p * 16 + ((lane >> 4) & 1) * 8 + (lane & 7)) * ROWB +
            ((lane >> 3) & 1) * 16;

    float acc[2][8][4];
#pragma unroll
    for (int mt = 0; mt < 2; mt++)
#pragma unroll
        for (int nt = 0; nt < 8; nt++)
#pragma unroll
            for (int r = 0; r < 4; r++) acc[mt][nt][r] = 0.f;

    load_chunk(0);

    for (int kt = 0; kt < NCHUNK; kt++) {
        mbar_wait((kt & 1) ? mb1 : mb0, (kt >> 1) & 1);
        __syncthreads();                  // everyone done with the other buffer
        if (kt + 1 < NCHUNK) load_chunk(kt + 1);

        const uint32_t st = sb + (uint32_t)(kt & 1) * STAGEB;
#pragma unroll
        for (int kk = 0; kk < 8; kk++) {
            uint32_t ah[2][4];
            LDSM_X4(ah[0], st + a_off[0] + kk * 32);
            LDSM_X4(ah[1], st + a_off[1] + kk * 32);
#pragma unroll
            for (int p = 0; p < 4; p++) {
                uint32_t bh[4];
                LDSM_X4(bh, st + b_off[p] + kk * 32);
#pragma unroll
                for (int mt = 0; mt < 2; mt++) {
                    MMA_F16(acc[mt][2 * p],     ah[mt][0], ah[mt][1], ah[mt][2], ah[mt][3], bh[0], bh[1]);
                    MMA_F16(acc[mt][2 * p + 1], ah[mt][0], ah[mt][1], ah[mt][2], ah[mt][3], bh[2], bh[3]);
                }
            }
        }
    }

    // ---- epilogue ----
    const int mrow = lane >> 2;
    const int cpair = (lane & 3) * 2;
    const int which = QKV ? (n0 >> 11) : 0;      // uniform per CTA
    const int nseg = QKV ? (n0 & 2047) : n0;
    const int h = nseg >> 7;
    const float* bp = QKV ? (which == 0 ? b0 : which == 1 ? b1 : b2) : b0;

#pragma unroll
    for (int mt = 0; mt < 2; mt++) {
#pragma unroll
        for (int rr = 0; rr < 2; rr++) {
            const int m = m0 + warp_m + mt * 16 + mrow + rr * 8;
            const int b = m >> 12;
            const int s = m & (Sc - 1);
#pragma unroll
            for (int nt = 0; nt < 8; nt++) {
                const int nl = warp_n + nt * 8 + cpair;     // 0..127
                float v0 = acc[mt][nt][rr * 2 + 0] + bp[nseg + nl];
                float v1 = acc[mt][nt][rr * 2 + 1] + bp[nseg + nl + 1];
                if (QKV) {
                    if (which < 2) {
                        const float cs = cosT[(size_t)s * Dc + nl];
                        const float sn = sinT[(size_t)s * Dc + nl];
                        const float e = v0 * cs - v1 * sn;
                        const float o_ = v1 * cs + v0 * sn;
                        v0 = fmaxf(e, 0.f);
                        v1 = fmaxf(o_, 0.f);
                    }
                    const size_t oi = (((size_t)b * Hc + h) * Sc + s) * Dc + nl;
                    if (which == 0)
                        *(uint32_t*)(g_Qh + oi) = pack_h2(v0, v1);
                    else if (which == 1)
                        *(float2*)(g_K + oi) = make_float2(v0, v1);
                    else
                        *(float2*)(g_V + oi) = make_float2(v0, v1);
                } else {
                    *(float2*)(dout + (size_t)m * Cc + nseg + nl) = make_float2(v0, v1);
                }
            }
        }
    }
}

// ======================= VK (fp32, unchanged) =======================
__global__ void __launch_bounds__(256) vk_kernel()
{
    const int bh = blockIdx.x;
    const int sp = blockIdx.y;
    const float* Vb = g_V + (size_t)bh * Sc * Dc;
    const float* Kb = g_K + (size_t)bh * Sc * Dc;

    __shared__ float Vs[16][128];
    __shared__ float Ks[16][128];

    const int tid = threadIdx.x;
    const int tx = tid & 15;
    const int ty = tid >> 4;
    const int lr = tid >> 5;
    const int lc = (tid & 31) * 4;

    float acc[8][8];
#pragma unroll
    for (int i = 0; i < 8; i++)
#pragma unroll
        for (int j = 0; j < 8; j++) acc[i][j] = 0.f;
    float csum = 0.f;

    const int schunk = Sc / NSPLIT;
    for (int st = 0; st < schunk / 16; st++) {
        const int s0 = sp * schunk + st * 16;
        __syncthreads();
        *(float4*)&Vs[lr][lc]     = *(const float4*)&Vb[(size_t)(s0 + lr) * Dc + lc];
        *(float4*)&Vs[lr + 8][lc] = *(const float4*)&Vb[(size_t)(s0 + lr + 8) * Dc + lc];
        *(float4*)&Ks[lr][lc]     = *(const float4*)&Kb[(size_t)(s0 + lr) * Dc + lc];
        *(float4*)&Ks[lr + 8][lc] = *(const float4*)&Kb[(size_t)(s0 + lr + 8) * Dc + lc];
        __syncthreads();
#pragma unroll
        for (int k = 0; k < 16; k++) {
            float4 a0 = *(const float4*)&Vs[k][ty * 8];
            float4 a1 = *(const float4*)&Vs[k][ty * 8 + 4];
            float4 b0 = *(const float4*)&Ks[k][tx * 8];
            float4 b1 = *(const float4*)&Ks[k][tx * 8 + 4];
            float av[8] = {a0.x, a0.y, a0.z, a0.w, a1.x, a1.y, a1.z, a1.w};
            float bv[8] = {b0.x, b0.y, b0.z, b0.w, b1.x, b1.y, b1.z, b1.w};
#pragma unroll
            for (int i = 0; i < 8; i++)
#pragma unroll
                for (int j = 0; j < 8; j++)
                    acc[i][j] = fmaf(av[i], bv[j], acc[i][j]);
        }
        if (tid < 128) {
#pragma unroll
            for (int k = 0; k < 16; k++) csum += Ks[k][tid];
        }
    }

    float* P = &g_VKpart[sp][(size_t)bh * 129 * Dc];
#pragma unroll
    for (int i = 0; i < 8; i++) {
        const int n = ty * 8 + i;
        *(float4*)&P[(size_t)n * Dc + tx * 8]     = make_float4(acc[i][0], acc[i][1], acc[i][2], acc[i][3]);
        *(float4*)&P[(size_t)n * Dc + tx * 8 + 4] = make_float4(acc[i][4], acc[i][5], acc[i][6], acc[i][7]);
    }
    if (tid < 128) P[(size_t)128 * Dc + tid] = csum;
}

__global__ void vk_reduce()
{
    const int i = blockIdx.x * 256 + threadIdx.x;
    if (i < Bc * Hc * 129 * Dc) {
        float s = 0.f;
#pragma unroll
        for (int p = 0; p < NSPLIT; p++) s += g_VKpart[p][i];
        g_VKh[i] = __float2half(s);
    }
}

// ======================= fp16 HMMA attn (unchanged from R9) =======================
#define QROW 272
#define SM_VK 34816                 // 128*272
#define SM_DEN (34816 + 35088)      // + 129*272

__global__ void __launch_bounds__(256) attn_mma()
{
    extern __shared__ __align__(16) char sm[];
    float* den = (float*)(sm + SM_DEN);

    const int bh = blockIdx.x;
    const int b = bh >> 4, h = bh & 15;
    const int s0 = blockIdx.y * 128;
    const int tid = threadIdx.x;
    const int lane = tid & 31;
    const int wid = tid >> 5;
    const int warp_m = (wid >> 1) * 32;   // s dim
    const int warp_n = (wid & 1) * 64;    // n dim

    const uint32_t sb = smem_u32(sm);

    const __half* Qg = g_Qh + ((size_t)bh * Sc + s0) * Dc;
    for (int idx = tid; idx < 128 * 16; idx += 256) {
        const int r = idx >> 4, c = idx & 15;
        *(uint4*)(sm + r * QROW + c * 16) = *(const uint4*)(Qg + (size_t)r * Dc + c * 8);
    }
    const __half* VKg = g_VKh + (size_t)bh * 129 * Dc;
    for (int idx = tid; idx < 129 * 16; idx += 256) {
        const int r = idx >> 4, c = idx & 15;
        *(uint4*)(sm + SM_VK + r * QROW + c * 16) = *(const uint4*)(VKg + (size_t)r * Dc + c * 8);
    }
    __syncthreads();

    float acc[2][8][4];
#pragma unroll
    for (int mt = 0; mt < 2; mt++)
#pragma unroll
        for (int nt = 0; nt < 8; nt++)
#pragma unroll
            for (int r = 0; r < 4; r++) acc[mt][nt][r] = 0.f;

    uint32_t a_addr[2];
#pragma unroll
    for (int mt = 0; mt < 2; mt++)
        a_addr[mt] = sb + (warp_m + mt * 16 + (lane & 15)) * QROW + (lane >> 4) * 16;
    uint32_t b_addr[4];
#pragma unroll
    for (int p = 0; p < 4; p++)
        b_addr[p] = sb + SM_VK +
            (warp_n + p * 16 + ((lane >> 4) & 1) * 8 + (lane & 7)) * QROW +
            ((lane >> 3) & 1) * 16;

#pragma unroll
    for (int ks = 0; ks < 8; ks++) {
        uint32_t ah[2][4];
        LDSM_X4(ah[0], a_addr[0] + ks * 32);
        LDSM_X4(ah[1], a_addr[1] + ks * 32);
#pragma unroll
        for (int p = 0; p < 4; p++) {
            uint32_t bhreg[4];
            LDSM_X4(bhreg, b_addr[p] + ks * 32);
#pragma unroll
            for (int mt = 0; mt < 2; mt++) {
                MMA_F16(acc[mt][2 * p],     ah[mt][0], ah[mt][1], ah[mt][2], ah[mt][3], bhreg[0], bhreg[1]);
                MMA_F16(acc[mt][2 * p + 1], ah[mt][0], ah[mt][1], ah[mt][2], ah[mt][3], bhreg[2], bhreg[3]);
            }
        }
    }

    if (tid < 128) {
        const __half2* vrow = (const __half2*)(sm + SM_VK + 128 * QROW);
        const __half2* qrow = (const __half2*)(sm + tid * QROW);
        float d = 0.f;
#pragma unroll 8
        for (int i = 0; i < 64; i++) {
            const float2 v = __half22float2(vrow[i]);
            const float2 q = __half22float2(qrow[i]);
            d = fmaf(v.x, q.x, d);
            d = fmaf(v.y, q.y, d);
        }
        den[tid] = 1.0f / (d + 1e-15f);
    }
    __syncthreads();

    const int mrow = lane >> 2;
    const int cpair = (lane & 3) * 2;
#pragma unroll
    for (int mt = 0; mt < 2; mt++) {
#pragma unroll
        for (int rr = 0; rr < 2; rr++) {
            const int m = warp_m + mt * 16 + mrow + rr * 8;    // s-local
            const float inv = den[m];
            __half* op = g_AThi + ((size_t)b * Sc + s0 + m) * Cc + h * Dc;
#pragma unroll
            for (int nt = 0; nt < 8; nt++) {
                const int n = warp_n + nt * 8 + cpair;
                *(uint32_t*)(op + n) =
                    pack_h2(acc[mt][nt][rr * 2] * inv, acc[mt][nt][rr * 2 + 1] * inv);
            }
        }
    }
}

// ======================= launch =======================
extern "C" void kernel_launch(void* const* d_in, const int* in_sizes, int n_in,
                              void* d_out, int out_size)
{
    (void)in_sizes; (void)n_in; (void)out_size;
    const float* x    = (const float*)d_in[0];
    const float* cosT = (const float*)d_in[1];
    const float* sinT = (const float*)d_in[2];
    const float* Wq   = (const float*)d_in[3];
    const float* bq   = (const float*)d_in[4];
    const float* Wk   = (const float*)d_in[5];
    const float* bk   = (const float*)d_in[6];
    const float* Wv   = (const float*)d_in[7];
    const float* bv   = (const float*)d_in[8];
    const float* Wo   = (const float*)d_in[9];
    const float* bo   = (const float*)d_in[10];
    float* out = (float*)d_out;

    __half *xhi, *whi, *athi;
    cudaGetSymbolAddress((void**)&xhi, g_Xhi);
    cudaGetSymbolAddress((void**)&whi, g_Whi);
    cudaGetSymbolAddress((void**)&athi, g_AThi);

    const size_t WSZ = (size_t)Cc * Cc;
    convert_hi<<<2048, 256>>>(x, xhi, (int)((size_t)Bc * Sc * Cc / 8));
    convert_hi<<<1024, 256>>>(Wq, whi + 0 * WSZ, (int)(WSZ / 8));
    convert_hi<<<1024, 256>>>(Wk, whi + 1 * WSZ, (int)(WSZ / 8));
    convert_hi<<<1024, 256>>>(Wv, whi + 2 * WSZ, (int)(WSZ / 8));
    convert_hi<<<1024, 256>>>(Wo, whi + 3 * WSZ, (int)(WSZ / 8));

    const int gsm = 2 * STAGEB;   // 208896
    cudaFuncSetAttribute(mma_gemm<0>, cudaFuncAttributeMaxDynamicSharedMemorySize, gsm);
    cudaFuncSetAttribute(mma_gemm<1>, cudaFuncAttributeMaxDynamicSharedMemorySize, gsm);

    // merged QKV: N = 6144, grid (48, 32)
    mma_gemm<1><<<dim3(48, 32), NT, gsm>>>(xhi, whi, bq, bk, bv, cosT, sinT, nullptr);

    vk_kernel<<<dim3(Bc * Hc, NSPLIT), 256>>>();
    vk_reduce<<<(Bc * Hc * 129 * Dc + 255) / 256, 256>>>();

    const int asm_ = SM_DEN + 128 * sizeof(float) + 16;   // ~70.4KB
    cudaFuncSetAttribute(attn_mma, cudaFuncAttributeMaxDynamicSharedMemorySize, asm_);
    attn_mma<<<dim3(Bc * Hc, Sc / 128), 256, asm_>>>();

    // O projection
    mma_gemm<0><<<dim3(16, 32), NT, gsm>>>(athi, whi + 3 * WSZ, bo, bo, bo,
                                           nullptr, nullptr, out);
}